// round 6
// baseline (speedup 1.0000x reference)
#include <cuda_runtime.h>
#include <cuda_bf16.h>
#include <cuda_fp16.h>
#include <cstdint>

typedef unsigned int uint;

#define MAX_N  100000
#define TILE_E 128

// Interleaved per-node table, 512 x 16-bit:
//  [0:128)   W src-half  (fp16)   [128:256) A src-half (bf16)
//  [256:384) W tgt-half  (fp16)   [384:512) A tgt-half (bf16)
static __device__ __half g_proj[(size_t)MAX_N * 512];

__device__ __forceinline__ uint cvt_tf32(float f) {
    uint r;
    asm("cvt.rna.tf32.f32 %0, %1;" : "=r"(r) : "f"(f));
    return r;
}

// ---------------------------------------------------------------- stage 1 ---
// proj-tile = emb(128 nodes x 128) @ [256-col weight block], tf32 HMMA.
// blockIdx.y = 0: W1 (fp16 out). 1: A1 (bf16 out).
#define SM_BS_BYTES 135168
#define SM_TOTAL    202752

__global__ void __launch_bounds__(512, 1)
precompute_kernel(const float* __restrict__ emb,
                  const float* __restrict__ W1,
                  const float* __restrict__ A1,
                  int N)
{
    extern __shared__ char sm[];
    uint* Bs = (uint*)sm;                    // [128][264] tf32
    uint* As = (uint*)(sm + SM_BS_BYTES);    // [128][132] tf32

    const int t    = threadIdx.x;
    const int base = blockIdx.x * 128;
    const int isA  = blockIdx.y;
    const float* __restrict__ Wm = isA ? A1 : W1;

    #pragma unroll
    for (int j = 0; j < 16; ++j) {
        int idx  = t + 512 * j;
        int krow = idx >> 5;
        int ch   = idx & 31;
        int koff = (krow >= 128) ? 128 : 0;
        int k    = krow - koff;
        float4 v = *(const float4*)&Wm[(size_t)krow * 128 + 4 * ch];
        uint* dst = &Bs[k * 264 + koff + 4 * ch];
        dst[0] = cvt_tf32(v.x); dst[1] = cvt_tf32(v.y);
        dst[2] = cvt_tf32(v.z); dst[3] = cvt_tf32(v.w);
    }
    #pragma unroll
    for (int j = 0; j < 8; ++j) {
        int idx = t + 512 * j;
        int row = idx >> 5;
        int q   = idx & 31;
        int n   = base + row; if (n >= N) n = N - 1;
        float4 v = ((const float4*)emb)[(size_t)n * 32 + q];
        uint* dst = &As[row * 132 + 4 * q];
        dst[0] = cvt_tf32(v.x); dst[1] = cvt_tf32(v.y);
        dst[2] = cvt_tf32(v.z); dst[3] = cvt_tf32(v.w);
    }
    __syncthreads();

    const int w = t >> 5, l = t & 31;
    const int wm = w >> 2, wn = w & 3;
    const int rbase = wm * 32;
    const int cbase = wn * 64;
    const int lq = l >> 2, lr = l & 3;

    float c[2][8][4];
    #pragma unroll
    for (int mt = 0; mt < 2; ++mt)
        #pragma unroll
        for (int nt = 0; nt < 8; ++nt)
            #pragma unroll
            for (int i = 0; i < 4; ++i) c[mt][nt][i] = 0.f;

    #pragma unroll
    for (int kt = 0; kt < 16; ++kt) {
        const int k0 = kt * 8;
        uint a[2][4];
        #pragma unroll
        for (int mt = 0; mt < 2; ++mt) {
            int r = rbase + mt * 16 + lq;
            a[mt][0] = As[r * 132 + k0 + lr];
            a[mt][1] = As[(r + 8) * 132 + k0 + lr];
            a[mt][2] = As[r * 132 + k0 + 4 + lr];
            a[mt][3] = As[(r + 8) * 132 + k0 + 4 + lr];
        }
        #pragma unroll
        for (int nt = 0; nt < 8; ++nt) {
            uint b0 = Bs[(k0 + lr) * 264 + cbase + nt * 8 + lq];
            uint b1 = Bs[(k0 + 4 + lr) * 264 + cbase + nt * 8 + lq];
            asm volatile("mma.sync.aligned.m16n8k8.row.col.f32.tf32.tf32.f32 "
                         "{%0,%1,%2,%3},{%4,%5,%6,%7},{%8,%9},{%0,%1,%2,%3};"
                         : "+f"(c[0][nt][0]), "+f"(c[0][nt][1]), "+f"(c[0][nt][2]), "+f"(c[0][nt][3])
                         : "r"(a[0][0]), "r"(a[0][1]), "r"(a[0][2]), "r"(a[0][3]),
                           "r"(b0), "r"(b1));
            asm volatile("mma.sync.aligned.m16n8k8.row.col.f32.tf32.tf32.f32 "
                         "{%0,%1,%2,%3},{%4,%5,%6,%7},{%8,%9},{%0,%1,%2,%3};"
                         : "+f"(c[1][nt][0]), "+f"(c[1][nt][1]), "+f"(c[1][nt][2]), "+f"(c[1][nt][3])
                         : "r"(a[1][0]), "r"(a[1][1]), "r"(a[1][2]), "r"(a[1][3]),
                           "r"(b0), "r"(b1));
        }
    }
    __syncthreads();

    // C fragments -> smem 16-bit (row stride 528 B)
    #pragma unroll
    for (int mt = 0; mt < 2; ++mt) {
        #pragma unroll
        for (int nt = 0; nt < 8; ++nt) {
            int r  = rbase + mt * 16 + lq;
            int cc = cbase + nt * 8 + 2 * lr;
            uint p01, p23;
            if (!isA) {
                __half2 h01 = __floats2half2_rn(c[mt][nt][0], c[mt][nt][1]);
                __half2 h23 = __floats2half2_rn(c[mt][nt][2], c[mt][nt][3]);
                p01 = *(uint*)&h01; p23 = *(uint*)&h23;
            } else {
                __nv_bfloat162 h01 = __floats2bfloat162_rn(c[mt][nt][0], c[mt][nt][1]);
                __nv_bfloat162 h23 = __floats2bfloat162_rn(c[mt][nt][2], c[mt][nt][3]);
                p01 = *(uint*)&h01; p23 = *(uint*)&h23;
            }
            *(uint*)(sm + r * 528 + cc * 2)       = p01;
            *(uint*)(sm + (r + 8) * 528 + cc * 2) = p23;
        }
    }
    __syncthreads();

    // Coalesced copy-out into the interleaved table.
    #pragma unroll
    for (int j = 0; j < 8; ++j) {
        int idx = t + 512 * j;          // 0..4095
        int row = idx >> 5, s = idx & 31;
        if (base + row < N) {
            uint4 v = *(uint4*)(sm + row * 528 + s * 16);
            int dstoff = isA * 128 + 8 * (s & 15) + (s >> 4) * 256;
            *(uint4*)&g_proj[(size_t)(base + row) * 512 + dstoff] = v;
        }
    }
}

// ---------------------------------------------------------------- stage 2 ---
struct S2 {
    __nv_bfloat16 ha[TILE_E][136];   // row stride 272 B (16B-aligned rows)
    __nv_bfloat16 A2s[128][72];      // row stride 144 B
    float ab2s[64];
    float pen[TILE_E];
    int   maxsend[TILE_E];
    int   srcs[TILE_E];
    int   tgts[TILE_E];
};

__global__ void __launch_bounds__(512)
edge_kernel(const int*   __restrict__ edges,
            const int*   __restrict__ army,
            const float* __restrict__ b1,
            const float* __restrict__ W2,
            const float* __restrict__ b2,
            const float* __restrict__ ab1,
            const float* __restrict__ A2,
            const float* __restrict__ ab2,
            float* __restrict__ out,
            int E)
{
    extern __shared__ char smem_raw[];
    S2* S = (S2*)smem_raw;
    const int t = threadIdx.x;
    const int blockBase = blockIdx.x * TILE_E;

    // A2 -> bf16 smem [k][n]
    #pragma unroll
    for (int i = 0; i < 8; ++i) {
        int fidx = t + 512 * i;
        int k = fidx >> 5, nq = fidx & 31;
        float2 v = ((const float2*)A2)[fidx];
        __nv_bfloat162 b = __floats2bfloat162_rn(v.x, v.y);
        *(__nv_bfloat162*)&S->A2s[k][nq * 2] = b;
    }
    if (t < 64) S->ab2s[t] = ab2[t];
    if (t < TILE_E) {
        int e = blockBase + t;
        int s = 0, g = 0, ms = -1; float pen = 0.f;
        if (e < E) {
            s = __ldcs(&edges[2 * e]); g = __ldcs(&edges[2 * e + 1]);
            int sa = army[s], ta = army[g];
            ms = sa - 1;
            if (sa <= 2 || ta >= 3 * sa) pen += 1.f;
            if (s == g) pen += 100.f;
        }
        S->srcs[t] = s; S->tgts[t] = g; S->maxsend[t] = ms; S->pen[t] = pen;
    }
    __syncthreads();

    const int w = t >> 5, l = t & 31;
    const __half* __restrict__ proj = g_proj;
    const bool isW = l < 16;
    const int f8 = (l & 15) * 8;          // feature base (0..120)

    // Per-lane constants: lanes 0-15 use b1/W2, lanes 16-31 use ab1.
    const float* cbp = isW ? b1 : ab1;
    float4 bbl = ((const float4*)(cbp + f8))[0];
    float4 bbh = ((const float4*)(cbp + f8))[1];
    float4 wwl = ((const float4*)(W2 + f8))[0];
    float4 wwh = ((const float4*)(W2 + f8))[1];
    const float b2v = b2[0];

    // Phase 1: 16 warps x 8 edges. 2x LDG.128 per lane per edge.
    const int wbase8 = w * 8;
    #pragma unroll 4
    for (int i = 0; i < 8; ++i) {
        const int le = wbase8 + i;
        const int e  = blockBase + le;
        const size_t sB = (size_t)S->srcs[le] * 512;
        const size_t tB = (size_t)S->tgts[le] * 512 + 256;
        uint4 sv = *(const uint4*)(proj + sB + 8 * l);
        uint4 tv = *(const uint4*)(proj + tB + 8 * l);

        if (isW) {
            float2 s0 = __half22float2(*(__half2*)&sv.x);
            float2 s1 = __half22float2(*(__half2*)&sv.y);
            float2 s2 = __half22float2(*(__half2*)&sv.z);
            float2 s3 = __half22float2(*(__half2*)&sv.w);
            float2 t0 = __half22float2(*(__half2*)&tv.x);
            float2 t1 = __half22float2(*(__half2*)&tv.y);
            float2 t2 = __half22float2(*(__half2*)&tv.z);
            float2 t3 = __half22float2(*(__half2*)&tv.w);
            float part;
            part  = fmaxf(s0.x + t0.x + bbl.x, 0.f) * wwl.x;
            part  = fmaf(fmaxf(s0.y + t0.y + bbl.y, 0.f), wwl.y, part);
            part  = fmaf(fmaxf(s1.x + t1.x + bbl.z, 0.f), wwl.z, part);
            part  = fmaf(fmaxf(s1.y + t1.y + bbl.w, 0.f), wwl.w, part);
            part  = fmaf(fmaxf(s2.x + t2.x + bbh.x, 0.f), wwh.x, part);
            part  = fmaf(fmaxf(s2.y + t2.y + bbh.y, 0.f), wwh.y, part);
            part  = fmaf(fmaxf(s3.x + t3.x + bbh.z, 0.f), wwh.z, part);
            part  = fmaf(fmaxf(s3.y + t3.y + bbh.w, 0.f), wwh.w, part);
            // 16-lane reduction: mask names exactly the participating lanes.
            #pragma unroll
            for (int d = 8; d > 0; d >>= 1)
                part += __shfl_xor_sync(0x0000ffffu, part, d);
            if (l == 0 && e < E) __stcs(&out[e], part + b2v - S->pen[le]);
        } else {
            float2 s0 = __bfloat1622float2(*(__nv_bfloat162*)&sv.x);
            float2 s1 = __bfloat1622float2(*(__nv_bfloat162*)&sv.y);
            float2 s2 = __bfloat1622float2(*(__nv_bfloat162*)&sv.z);
            float2 s3 = __bfloat1622float2(*(__nv_bfloat162*)&sv.w);
            float2 t0 = __bfloat1622float2(*(__nv_bfloat162*)&tv.x);
            float2 t1 = __bfloat1622float2(*(__nv_bfloat162*)&tv.y);
            float2 t2 = __bfloat1622float2(*(__nv_bfloat162*)&tv.z);
            float2 t3 = __bfloat1622float2(*(__nv_bfloat162*)&tv.w);
            __nv_bfloat162 g0 = __floats2bfloat162_rn(fmaxf(s0.x + t0.x + bbl.x, 0.f),
                                                      fmaxf(s0.y + t0.y + bbl.y, 0.f));
            __nv_bfloat162 g1 = __floats2bfloat162_rn(fmaxf(s1.x + t1.x + bbl.z, 0.f),
                                                      fmaxf(s1.y + t1.y + bbl.w, 0.f));
            __nv_bfloat162 g2 = __floats2bfloat162_rn(fmaxf(s2.x + t2.x + bbh.x, 0.f),
                                                      fmaxf(s2.y + t2.y + bbh.y, 0.f));
            __nv_bfloat162 g3 = __floats2bfloat162_rn(fmaxf(s3.x + t3.x + bbh.z, 0.f),
                                                      fmaxf(s3.y + t3.y + bbh.w, 0.f));
            uint4 stv;
            stv.x = *(uint*)&g0; stv.y = *(uint*)&g1;
            stv.z = *(uint*)&g2; stv.w = *(uint*)&g3;
            *(uint4*)&S->ha[le][f8] = stv;
        }
    }
    __syncthreads();

    // Phase 2: warp = (m-tile of 16 edges, 32-col half). 16 warps cover 8x2.
    const int mtile  = w >> 1;
    const int cbase  = (w & 1) * 32;
    const int wbase16 = mtile * 16;

    float c[4][4];
    #pragma unroll
    for (int nt = 0; nt < 4; ++nt) {
        float2 ab = *(const float2*)&S->ab2s[cbase + nt * 8 + 2 * (l & 3)];
        c[nt][0] = ab.x; c[nt][1] = ab.y; c[nt][2] = ab.x; c[nt][3] = ab.y;
    }
    unsigned haBase = (unsigned)__cvta_generic_to_shared(&S->ha[0][0]);
    unsigned a2Base = (unsigned)__cvta_generic_to_shared(&S->A2s[0][0]);
    const int m = l >> 3;
    const int arow = wbase16 + (l & 7) + (m & 1) * 8;
    const int akof = (m >> 1) * 8;
    const int bkoff = (l & 7) + (m & 1) * 8;
    const int bnoff = (m >> 1) * 8;

    #pragma unroll
    for (int ks = 0; ks < 8; ++ks) {
        const int k0 = ks * 16;
        unsigned a0, a1, a2, a3;
        unsigned aaddr = haBase + (unsigned)(arow * 272 + (k0 + akof) * 2);
        asm volatile("ldmatrix.sync.aligned.m8n8.x4.shared.b16 {%0,%1,%2,%3}, [%4];"
                     : "=r"(a0), "=r"(a1), "=r"(a2), "=r"(a3) : "r"(aaddr));
        #pragma unroll
        for (int nt2 = 0; nt2 < 2; ++nt2) {
            unsigned b0, b1r, b2r, b3r;
            unsigned baddr = a2Base + (unsigned)((k0 + bkoff) * 144 + (cbase + nt2 * 16 + bnoff) * 2);
            asm volatile("ldmatrix.sync.aligned.m8n8.x4.trans.shared.b16 {%0,%1,%2,%3}, [%4];"
                         : "=r"(b0), "=r"(b1r), "=r"(b2r), "=r"(b3r) : "r"(baddr));
            asm volatile("mma.sync.aligned.m16n8k16.row.col.f32.bf16.bf16.f32 "
                         "{%0,%1,%2,%3},{%4,%5,%6,%7},{%8,%9},{%0,%1,%2,%3};"
                         : "+f"(c[2*nt2][0]), "+f"(c[2*nt2][1]), "+f"(c[2*nt2][2]), "+f"(c[2*nt2][3])
                         : "r"(a0), "r"(a1), "r"(a2), "r"(a3), "r"(b0), "r"(b1r));
            asm volatile("mma.sync.aligned.m16n8k16.row.col.f32.bf16.bf16.f32 "
                         "{%0,%1,%2,%3},{%4,%5,%6,%7},{%8,%9},{%0,%1,%2,%3};"
                         : "+f"(c[2*nt2+1][0]), "+f"(c[2*nt2+1][1]), "+f"(c[2*nt2+1][2]), "+f"(c[2*nt2+1][3])
                         : "r"(a0), "r"(a1), "r"(a2), "r"(a3), "r"(b2r), "r"(b3r));
        }
    }

    // Epilogue: mask + streaming stores.
    const int r0 = wbase16 + (l >> 2);
    const int e0 = blockBase + r0;
    const int e1 = e0 + 8;
    const int ms0 = S->maxsend[r0];
    const int ms1 = S->maxsend[r0 + 8];
    #pragma unroll
    for (int nt = 0; nt < 4; ++nt) {
        const int col = cbase + nt * 8 + 2 * (l & 3);
        if (e0 < E) {
            float2 v;
            v.x = (col     <= ms0) ? c[nt][0] : -1.0e9f;
            v.y = (col + 1 <= ms0) ? c[nt][1] : -1.0e9f;
            __stcs((float2*)&out[(size_t)E + (size_t)e0 * 64 + col], v);
        }
        if (e1 < E) {
            float2 v;
            v.x = (col     <= ms1) ? c[nt][2] : -1.0e9f;
            v.y = (col + 1 <= ms1) ? c[nt][3] : -1.0e9f;
            __stcs((float2*)&out[(size_t)E + (size_t)e1 * 64 + col], v);
        }
    }
}

// ---------------------------------------------------------------- launch ----
extern "C" void kernel_launch(void* const* d_in, const int* in_sizes, int n_in,
                              void* d_out, int out_size)
{
    const float* emb   = (const float*)d_in[0];
    const int*   edges = (const int*)  d_in[1];
    const int*   army  = (const int*)  d_in[2];
    const float* W1    = (const float*)d_in[3];
    const float* b1    = (const float*)d_in[4];
    const float* W2    = (const float*)d_in[5];
    const float* b2    = (const float*)d_in[6];
    const float* A1    = (const float*)d_in[7];
    const float* ab1   = (const float*)d_in[8];
    const float* A2    = (const float*)d_in[9];
    const float* ab2   = (const float*)d_in[10];
    float* out = (float*)d_out;

    int N = in_sizes[0] / 128;
    int E = in_sizes[1] / 2;
    if (N > MAX_N) N = MAX_N;

    cudaFuncSetAttribute(precompute_kernel,
                         cudaFuncAttributeMaxDynamicSharedMemorySize, SM_TOTAL);
    dim3 g1((N + 127) / 128, 2);
    precompute_kernel<<<g1, 512, SM_TOTAL>>>(emb, W1, A1, N);

    cudaFuncSetAttribute(edge_kernel, cudaFuncAttributeMaxDynamicSharedMemorySize,
                         (int)sizeof(S2));
    edge_kernel<<<(E + TILE_E - 1) / TILE_E, 512, sizeof(S2)>>>(
        edges, army, b1, W2, b2, ab1, A2, ab2, out, E);
}

// round 7
// speedup vs baseline: 1.2257x; 1.2257x over previous
#include <cuda_runtime.h>
#include <cuda_bf16.h>
#include <cuda_fp16.h>
#include <cstdint>

typedef unsigned int uint;

#define MAX_N  100000
#define TILE_E 64

// Interleaved per-node table, 512 x 16-bit:
//  [0:128)   W src-half  (fp16)   [128:256) A src-half (bf16)
//  [256:384) W tgt-half  (fp16)   [384:512) A tgt-half (bf16)
static __device__ __half g_proj[(size_t)MAX_N * 512];
static __device__ __nv_bfloat16 g_A2[128 * 64];   // A2 pre-converted to bf16

__device__ __forceinline__ uint cvt_tf32(float f) {
    uint r;
    asm("cvt.rna.tf32.f32 %0, %1;" : "=r"(r) : "f"(f));
    return r;
}

// ------------------------------------------------------------- a2 prep ------
__global__ void __launch_bounds__(256)
a2prep_kernel(const float* __restrict__ A2)
{
    const int t = threadIdx.x;
    #pragma unroll
    for (int i = 0; i < 16; ++i) {
        int idx = t + 256 * i;                 // 0..4095 float2
        float2 v = ((const float2*)A2)[idx];
        __nv_bfloat162 b = __floats2bfloat162_rn(v.x, v.y);
        *(__nv_bfloat162*)&g_A2[idx * 2] = b;
    }
}

// ---------------------------------------------------------------- stage 1 ---
// proj-tile = emb(128 nodes x 128) @ [256-col weight block], tf32 HMMA.
// blockIdx.y = 0: W1 (fp16 out). 1: A1 (bf16 out).
#define SM_BS_BYTES 135168
#define SM_TOTAL    202752

__global__ void __launch_bounds__(512, 1)
precompute_kernel(const float* __restrict__ emb,
                  const float* __restrict__ W1,
                  const float* __restrict__ A1,
                  int N)
{
    extern __shared__ char sm[];
    uint* Bs = (uint*)sm;                    // [128][264] tf32
    uint* As = (uint*)(sm + SM_BS_BYTES);    // [128][132] tf32

    const int t    = threadIdx.x;
    const int base = blockIdx.x * 128;
    const int isA  = blockIdx.y;
    const float* __restrict__ Wm = isA ? A1 : W1;

    #pragma unroll
    for (int j = 0; j < 16; ++j) {
        int idx  = t + 512 * j;
        int krow = idx >> 5;
        int ch   = idx & 31;
        int koff = (krow >= 128) ? 128 : 0;
        int k    = krow - koff;
        float4 v = *(const float4*)&Wm[(size_t)krow * 128 + 4 * ch];
        uint* dst = &Bs[k * 264 + koff + 4 * ch];
        dst[0] = cvt_tf32(v.x); dst[1] = cvt_tf32(v.y);
        dst[2] = cvt_tf32(v.z); dst[3] = cvt_tf32(v.w);
    }
    #pragma unroll
    for (int j = 0; j < 8; ++j) {
        int idx = t + 512 * j;
        int row = idx >> 5;
        int q   = idx & 31;
        int n   = base + row; if (n >= N) n = N - 1;
        float4 v = ((const float4*)emb)[(size_t)n * 32 + q];
        uint* dst = &As[row * 132 + 4 * q];
        dst[0] = cvt_tf32(v.x); dst[1] = cvt_tf32(v.y);
        dst[2] = cvt_tf32(v.z); dst[3] = cvt_tf32(v.w);
    }
    __syncthreads();

    const int w = t >> 5, l = t & 31;
    const int wm = w >> 2, wn = w & 3;
    const int rbase = wm * 32;
    const int cbase = wn * 64;
    const int lq = l >> 2, lr = l & 3;

    float c[2][8][4];
    #pragma unroll
    for (int mt = 0; mt < 2; ++mt)
        #pragma unroll
        for (int nt = 0; nt < 8; ++nt)
            #pragma unroll
            for (int i = 0; i < 4; ++i) c[mt][nt][i] = 0.f;

    #pragma unroll
    for (int kt = 0; kt < 16; ++kt) {
        const int k0 = kt * 8;
        uint a[2][4];
        #pragma unroll
        for (int mt = 0; mt < 2; ++mt) {
            int r = rbase + mt * 16 + lq;
            a[mt][0] = As[r * 132 + k0 + lr];
            a[mt][1] = As[(r + 8) * 132 + k0 + lr];
            a[mt][2] = As[r * 132 + k0 + 4 + lr];
            a[mt][3] = As[(r + 8) * 132 + k0 + 4 + lr];
        }
        #pragma unroll
        for (int nt = 0; nt < 8; ++nt) {
            uint b0 = Bs[(k0 + lr) * 264 + cbase + nt * 8 + lq];
            uint b1 = Bs[(k0 + 4 + lr) * 264 + cbase + nt * 8 + lq];
            asm volatile("mma.sync.aligned.m16n8k8.row.col.f32.tf32.tf32.f32 "
                         "{%0,%1,%2,%3},{%4,%5,%6,%7},{%8,%9},{%0,%1,%2,%3};"
                         : "+f"(c[0][nt][0]), "+f"(c[0][nt][1]), "+f"(c[0][nt][2]), "+f"(c[0][nt][3])
                         : "r"(a[0][0]), "r"(a[0][1]), "r"(a[0][2]), "r"(a[0][3]),
                           "r"(b0), "r"(b1));
            asm volatile("mma.sync.aligned.m16n8k8.row.col.f32.tf32.tf32.f32 "
                         "{%0,%1,%2,%3},{%4,%5,%6,%7},{%8,%9},{%0,%1,%2,%3};"
                         : "+f"(c[1][nt][0]), "+f"(c[1][nt][1]), "+f"(c[1][nt][2]), "+f"(c[1][nt][3])
                         : "r"(a[1][0]), "r"(a[1][1]), "r"(a[1][2]), "r"(a[1][3]),
                           "r"(b0), "r"(b1));
        }
    }
    __syncthreads();

    // C fragments -> smem 16-bit (row stride 528 B)
    #pragma unroll
    for (int mt = 0; mt < 2; ++mt) {
        #pragma unroll
        for (int nt = 0; nt < 8; ++nt) {
            int r  = rbase + mt * 16 + lq;
            int cc = cbase + nt * 8 + 2 * lr;
            uint p01, p23;
            if (!isA) {
                __half2 h01 = __floats2half2_rn(c[mt][nt][0], c[mt][nt][1]);
                __half2 h23 = __floats2half2_rn(c[mt][nt][2], c[mt][nt][3]);
                p01 = *(uint*)&h01; p23 = *(uint*)&h23;
            } else {
                __nv_bfloat162 h01 = __floats2bfloat162_rn(c[mt][nt][0], c[mt][nt][1]);
                __nv_bfloat162 h23 = __floats2bfloat162_rn(c[mt][nt][2], c[mt][nt][3]);
                p01 = *(uint*)&h01; p23 = *(uint*)&h23;
            }
            *(uint*)(sm + r * 528 + cc * 2)       = p01;
            *(uint*)(sm + (r + 8) * 528 + cc * 2) = p23;
        }
    }
    __syncthreads();

    // Coalesced copy-out into the interleaved table.
    #pragma unroll
    for (int j = 0; j < 8; ++j) {
        int idx = t + 512 * j;          // 0..4095
        int row = idx >> 5, s = idx & 31;
        if (base + row < N) {
            uint4 v = *(uint4*)(sm + row * 528 + s * 16);
            int dstoff = isA * 128 + 8 * (s & 15) + (s >> 4) * 256;
            *(uint4*)&g_proj[(size_t)(base + row) * 512 + dstoff] = v;
        }
    }
}

// ---------------------------------------------------------------- stage 2 ---
struct S2 {
    __nv_bfloat16 ha[TILE_E][136];   // 17408 B, row stride 272 B
    __nv_bfloat16 A2s[128][72];      // 18432 B, row stride 144 B
    float ab2s[64];
    float pen[TILE_E];
    int   maxsend[TILE_E];
    int   srcs[TILE_E];
    int   tgts[TILE_E];
};

__global__ void __launch_bounds__(256, 6)
edge_kernel(const int*   __restrict__ edges,
            const int*   __restrict__ army,
            const float* __restrict__ b1,
            const float* __restrict__ W2,
            const float* __restrict__ b2,
            const float* __restrict__ ab1,
            const float* __restrict__ ab2,
            float* __restrict__ out,
            int E)
{
    extern __shared__ char smem_raw[];
    S2* S = (S2*)smem_raw;
    const int t = threadIdx.x;
    const int blockBase = blockIdx.x * TILE_E;

    // A2 (pre-converted bf16) -> smem padded [k][64 of 72]
    #pragma unroll
    for (int i = 0; i < 4; ++i) {
        int idx = t + 256 * i;               // 0..1023 uint4
        int k = idx >> 3, chunk = idx & 7;
        uint4 v = *(const uint4*)&g_A2[idx * 8];
        *(uint4*)&S->A2s[k][chunk * 8] = v;
    }
    if (t < 64) S->ab2s[t] = ab2[t];
    if (t < TILE_E) {
        int e = blockBase + t;
        int s = 0, g = 0, ms = -1; float pen = 0.f;
        if (e < E) {
            s = __ldcs(&edges[2 * e]); g = __ldcs(&edges[2 * e + 1]);
            int sa = army[s], ta = army[g];
            ms = sa - 1;
            if (sa <= 2 || ta >= 3 * sa) pen += 1.f;
            if (s == g) pen += 100.f;
        }
        S->srcs[t] = s; S->tgts[t] = g; S->maxsend[t] = ms; S->pen[t] = pen;
    }
    __syncthreads();

    const int w = t >> 5, l = t & 31;
    const __half* __restrict__ proj = g_proj;

    float4 b1v  = ((const float4*)b1)[l];
    float4 ab1v = ((const float4*)ab1)[l];
    float4 w2v  = ((const float4*)W2)[l];
    const float b2v = b2[0];

    // Phase 1: 8 warps x 8 edges, full warp per edge (no divergence).
    // Lane l owns features 4l..4l+3. 4x LDG.64 per lane per edge.
    const int wbase8 = w * 8;
    #pragma unroll 2
    for (int i = 0; i < 8; ++i) {
        const int le = wbase8 + i;
        const int e  = blockBase + le;
        const size_t sB = (size_t)S->srcs[le] * 512;
        const size_t tB = (size_t)S->tgts[le] * 512;
        uint2 ws = *(const uint2*)(proj + sB + 4 * l);          // W src (fp16)
        uint2 wt = *(const uint2*)(proj + tB + 256 + 4 * l);    // W tgt (fp16)
        uint2 pa = *(const uint2*)(proj + sB + 128 + 4 * l);    // A src (bf16)
        uint2 pt = *(const uint2*)(proj + tB + 384 + 4 * l);    // A tgt (bf16)

        float2 s01 = __half22float2(*(__half2*)&ws.x);
        float2 s23 = __half22float2(*(__half2*)&ws.y);
        float2 t01 = __half22float2(*(__half2*)&wt.x);
        float2 t23 = __half22float2(*(__half2*)&wt.y);
        float h0 = fmaxf(s01.x + t01.x + b1v.x, 0.f);
        float h1 = fmaxf(s01.y + t01.y + b1v.y, 0.f);
        float h2 = fmaxf(s23.x + t23.x + b1v.z, 0.f);
        float h3 = fmaxf(s23.y + t23.y + b1v.w, 0.f);
        float part = fmaf(h0, w2v.x, fmaf(h1, w2v.y, fmaf(h2, w2v.z, h3 * w2v.w)));
        #pragma unroll
        for (int d = 16; d > 0; d >>= 1)
            part += __shfl_xor_sync(0xffffffffu, part, d);
        if (l == 0 && e < E) __stcs(&out[e], part + b2v - S->pen[le]);

        float2 fa0 = __bfloat1622float2(*(__nv_bfloat162*)&pa.x);
        float2 fa1 = __bfloat1622float2(*(__nv_bfloat162*)&pa.y);
        float2 ft0 = __bfloat1622float2(*(__nv_bfloat162*)&pt.x);
        float2 ft1 = __bfloat1622float2(*(__nv_bfloat162*)&pt.y);
        float g0 = fmaxf(fa0.x + ft0.x + ab1v.x, 0.f);
        float g1 = fmaxf(fa0.y + ft0.y + ab1v.y, 0.f);
        float g2 = fmaxf(fa1.x + ft1.x + ab1v.z, 0.f);
        float g3 = fmaxf(fa1.y + ft1.y + ab1v.w, 0.f);
        __nv_bfloat162 hh0 = __floats2bfloat162_rn(g0, g1);
        __nv_bfloat162 hh1 = __floats2bfloat162_rn(g2, g3);
        uint2 stv; stv.x = *(uint*)&hh0; stv.y = *(uint*)&hh1;
        *(uint2*)&S->ha[le][4 * l] = stv;
    }
    __syncthreads();

    // Phase 2: warp = (m-tile of 16 edges, 32-col half). 8 warps cover 4x2.
    const int mtile   = w >> 1;
    const int cbase   = (w & 1) * 32;
    const int wbase16 = mtile * 16;

    float c[4][4];
    #pragma unroll
    for (int nt = 0; nt < 4; ++nt) {
        float2 ab = *(const float2*)&S->ab2s[cbase + nt * 8 + 2 * (l & 3)];
        c[nt][0] = ab.x; c[nt][1] = ab.y; c[nt][2] = ab.x; c[nt][3] = ab.y;
    }
    unsigned haBase = (unsigned)__cvta_generic_to_shared(&S->ha[0][0]);
    unsigned a2Base = (unsigned)__cvta_generic_to_shared(&S->A2s[0][0]);
    const int m = l >> 3;
    const int arow = wbase16 + (l & 7) + (m & 1) * 8;
    const int akof = (m >> 1) * 8;
    const int bkoff = (l & 7) + (m & 1) * 8;
    const int bnoff = (m >> 1) * 8;

    #pragma unroll
    for (int ks = 0; ks < 8; ++ks) {
        const int k0 = ks * 16;
        unsigned a0, a1, a2, a3;
        unsigned aaddr = haBase + (unsigned)(arow * 272 + (k0 + akof) * 2);
        asm volatile("ldmatrix.sync.aligned.m8n8.x4.shared.b16 {%0,%1,%2,%3}, [%4];"
                     : "=r"(a0), "=r"(a1), "=r"(a2), "=r"(a3) : "r"(aaddr));
        #pragma unroll
        for (int nt2 = 0; nt2 < 2; ++nt2) {
            unsigned b0, b1r, b2r, b3r;
            unsigned baddr = a2Base + (unsigned)((k0 + bkoff) * 144 + (cbase + nt2 * 16 + bnoff) * 2);
            asm volatile("ldmatrix.sync.aligned.m8n8.x4.trans.shared.b16 {%0,%1,%2,%3}, [%4];"
                         : "=r"(b0), "=r"(b1r), "=r"(b2r), "=r"(b3r) : "r"(baddr));
            asm volatile("mma.sync.aligned.m16n8k16.row.col.f32.bf16.bf16.f32 "
                         "{%0,%1,%2,%3},{%4,%5,%6,%7},{%8,%9},{%0,%1,%2,%3};"
                         : "+f"(c[2*nt2][0]), "+f"(c[2*nt2][1]), "+f"(c[2*nt2][2]), "+f"(c[2*nt2][3])
                         : "r"(a0), "r"(a1), "r"(a2), "r"(a3), "r"(b0), "r"(b1r));
            asm volatile("mma.sync.aligned.m16n8k16.row.col.f32.bf16.bf16.f32 "
                         "{%0,%1,%2,%3},{%4,%5,%6,%7},{%8,%9},{%0,%1,%2,%3};"
                         : "+f"(c[2*nt2+1][0]), "+f"(c[2*nt2+1][1]), "+f"(c[2*nt2+1][2]), "+f"(c[2*nt2+1][3])
                         : "r"(a0), "r"(a1), "r"(a2), "r"(a3), "r"(b2r), "r"(b3r));
        }
    }

    // Epilogue: mask + streaming stores.
    const int r0 = wbase16 + (l >> 2);
    const int e0 = blockBase + r0;
    const int e1 = e0 + 8;
    const int ms0 = S->maxsend[r0];
    const int ms1 = S->maxsend[r0 + 8];
    #pragma unroll
    for (int nt = 0; nt < 4; ++nt) {
        const int col = cbase + nt * 8 + 2 * (l & 3);
        if (e0 < E) {
            float2 v;
            v.x = (col     <= ms0) ? c[nt][0] : -1.0e9f;
            v.y = (col + 1 <= ms0) ? c[nt][1] : -1.0e9f;
            __stcs((float2*)&out[(size_t)E + (size_t)e0 * 64 + col], v);
        }
        if (e1 < E) {
            float2 v;
            v.x = (col     <= ms1) ? c[nt][2] : -1.0e9f;
            v.y = (col + 1 <= ms1) ? c[nt][3] : -1.0e9f;
            __stcs((float2*)&out[(size_t)E + (size_t)e1 * 64 + col], v);
        }
    }
}

// ---------------------------------------------------------------- launch ----
extern "C" void kernel_launch(void* const* d_in, const int* in_sizes, int n_in,
                              void* d_out, int out_size)
{
    const float* emb   = (const float*)d_in[0];
    const int*   edges = (const int*)  d_in[1];
    const int*   army  = (const int*)  d_in[2];
    const float* W1    = (const float*)d_in[3];
    const float* b1    = (const float*)d_in[4];
    const float* W2    = (const float*)d_in[5];
    const float* b2    = (const float*)d_in[6];
    const float* A1    = (const float*)d_in[7];
    const float* ab1   = (const float*)d_in[8];
    const float* A2    = (const float*)d_in[9];
    const float* ab2   = (const float*)d_in[10];
    float* out = (float*)d_out;

    int N = in_sizes[0] / 128;
    int E = in_sizes[1] / 2;
    if (N > MAX_N) N = MAX_N;

    a2prep_kernel<<<1, 256>>>(A2);

    cudaFuncSetAttribute(precompute_kernel,
                         cudaFuncAttributeMaxDynamicSharedMemorySize, SM_TOTAL);
    dim3 g1((N + 127) / 128, 2);
    precompute_kernel<<<g1, 512, SM_TOTAL>>>(emb, W1, A1, N);

    cudaFuncSetAttribute(edge_kernel, cudaFuncAttributeMaxDynamicSharedMemorySize,
                         (int)sizeof(S2));
    edge_kernel<<<(E + TILE_E - 1) / TILE_E, 256, sizeof(S2)>>>(
        edges, army, b1, W2, b2, ab1, ab2, out, E);
}

// round 8
// speedup vs baseline: 1.3590x; 1.1087x over previous
#include <cuda_runtime.h>
#include <cuda_bf16.h>
#include <cuda_fp16.h>
#include <cstdint>

typedef unsigned int uint;

#define MAX_N  100000
#define TILE_E 64

// Interleaved per-node table, 768 bytes:
//  [0:256)    W src-half: 128 fp16
//  [256:384)  A src-half: 128 e4m3
//  [384:640)  W tgt-half: 128 fp16
//  [640:768)  A tgt-half: 128 e4m3
static __device__ unsigned char g_proj[(size_t)MAX_N * 768];
static __device__ __nv_bfloat16 g_A2[128 * 64];   // A2 pre-converted to bf16

__device__ __forceinline__ uint cvt_tf32(float f) {
    uint r;
    asm("cvt.rna.tf32.f32 %0, %1;" : "=r"(r) : "f"(f));
    return r;
}

// pack two floats -> b16 of two e4m3 (lo=f0, hi=f1)
__device__ __forceinline__ unsigned short pack_e4m3_2(float f0, float f1) {
    unsigned short r;
    asm("cvt.rn.satfinite.e4m3x2.f32 %0, %2, %1;" : "=h"(r) : "f"(f0), "f"(f1));
    return r;
}

// unpack uint of 4 e4m3 -> two half2
__device__ __forceinline__ void unpack_e4m3_4(uint v, uint& h01, uint& h23) {
    asm("{\n\t.reg .b16 lo, hi;\n\t"
        "mov.b32 {lo, hi}, %2;\n\t"
        "cvt.rn.f16x2.e4m3x2 %0, lo;\n\t"
        "cvt.rn.f16x2.e4m3x2 %1, hi;\n\t}"
        : "=r"(h01), "=r"(h23) : "r"(v));
}

// ------------------------------------------------------------- a2 prep ------
__global__ void __launch_bounds__(256)
a2prep_kernel(const float* __restrict__ A2)
{
    int idx = blockIdx.x * 256 + threadIdx.x;   // 4096 float2 over 16 blocks
    #pragma unroll
    for (int i = 0; i < 1; ++i) {
        float2 v = ((const float2*)A2)[idx];
        __nv_bfloat162 b = __floats2bfloat162_rn(v.x, v.y);
        *(__nv_bfloat162*)&g_A2[idx * 2] = b;
    }
}

// ---------------------------------------------------------------- stage 1 ---
// proj-tile = emb(128 nodes x 128) @ [256-col weight block], tf32 HMMA.
// blockIdx.y = 0: W1 (fp16 out). 1: A1 (e4m3 out).
#define SM_BS_BYTES 135168
#define SM_TOTAL    202752

__global__ void __launch_bounds__(512, 1)
precompute_kernel(const float* __restrict__ emb,
                  const float* __restrict__ W1,
                  const float* __restrict__ A1,
                  int N)
{
    extern __shared__ char sm[];
    uint* Bs = (uint*)sm;                    // [128][264] tf32
    uint* As = (uint*)(sm + SM_BS_BYTES);    // [128][132] tf32

    const int t    = threadIdx.x;
    const int base = blockIdx.x * 128;
    const int isA  = blockIdx.y;
    const float* __restrict__ Wm = isA ? A1 : W1;

    #pragma unroll
    for (int j = 0; j < 16; ++j) {
        int idx  = t + 512 * j;
        int krow = idx >> 5;
        int ch   = idx & 31;
        int koff = (krow >= 128) ? 128 : 0;
        int k    = krow - koff;
        float4 v = *(const float4*)&Wm[(size_t)krow * 128 + 4 * ch];
        uint* dst = &Bs[k * 264 + koff + 4 * ch];
        dst[0] = cvt_tf32(v.x); dst[1] = cvt_tf32(v.y);
        dst[2] = cvt_tf32(v.z); dst[3] = cvt_tf32(v.w);
    }
    #pragma unroll
    for (int j = 0; j < 8; ++j) {
        int idx = t + 512 * j;
        int row = idx >> 5;
        int q   = idx & 31;
        int n   = base + row; if (n >= N) n = N - 1;
        float4 v = ((const float4*)emb)[(size_t)n * 32 + q];
        uint* dst = &As[row * 132 + 4 * q];
        dst[0] = cvt_tf32(v.x); dst[1] = cvt_tf32(v.y);
        dst[2] = cvt_tf32(v.z); dst[3] = cvt_tf32(v.w);
    }
    __syncthreads();

    const int w = t >> 5, l = t & 31;
    const int wm = w >> 2, wn = w & 3;
    const int rbase = wm * 32;
    const int cbase = wn * 64;
    const int lq = l >> 2, lr = l & 3;

    float c[2][8][4];
    #pragma unroll
    for (int mt = 0; mt < 2; ++mt)
        #pragma unroll
        for (int nt = 0; nt < 8; ++nt)
            #pragma unroll
            for (int i = 0; i < 4; ++i) c[mt][nt][i] = 0.f;

    #pragma unroll
    for (int kt = 0; kt < 16; ++kt) {
        const int k0 = kt * 8;
        uint a[2][4];
        #pragma unroll
        for (int mt = 0; mt < 2; ++mt) {
            int r = rbase + mt * 16 + lq;
            a[mt][0] = As[r * 132 + k0 + lr];
            a[mt][1] = As[(r + 8) * 132 + k0 + lr];
            a[mt][2] = As[r * 132 + k0 + 4 + lr];
            a[mt][3] = As[(r + 8) * 132 + k0 + 4 + lr];
        }
        #pragma unroll
        for (int nt = 0; nt < 8; ++nt) {
            uint b0 = Bs[(k0 + lr) * 264 + cbase + nt * 8 + lq];
            uint b1 = Bs[(k0 + 4 + lr) * 264 + cbase + nt * 8 + lq];
            asm volatile("mma.sync.aligned.m16n8k8.row.col.f32.tf32.tf32.f32 "
                         "{%0,%1,%2,%3},{%4,%5,%6,%7},{%8,%9},{%0,%1,%2,%3};"
                         : "+f"(c[0][nt][0]), "+f"(c[0][nt][1]), "+f"(c[0][nt][2]), "+f"(c[0][nt][3])
                         : "r"(a[0][0]), "r"(a[0][1]), "r"(a[0][2]), "r"(a[0][3]),
                           "r"(b0), "r"(b1));
            asm volatile("mma.sync.aligned.m16n8k8.row.col.f32.tf32.tf32.f32 "
                         "{%0,%1,%2,%3},{%4,%5,%6,%7},{%8,%9},{%0,%1,%2,%3};"
                         : "+f"(c[1][nt][0]), "+f"(c[1][nt][1]), "+f"(c[1][nt][2]), "+f"(c[1][nt][3])
                         : "r"(a[1][0]), "r"(a[1][1]), "r"(a[1][2]), "r"(a[1][3]),
                           "r"(b0), "r"(b1));
        }
    }
    __syncthreads();

    if (!isA) {
        // Stage fp16, row stride 528 B.
        #pragma unroll
        for (int mt = 0; mt < 2; ++mt) {
            #pragma unroll
            for (int nt = 0; nt < 8; ++nt) {
                int r  = rbase + mt * 16 + lq;
                int cc = cbase + nt * 8 + 2 * lr;
                __half2 h01 = __floats2half2_rn(c[mt][nt][0], c[mt][nt][1]);
                __half2 h23 = __floats2half2_rn(c[mt][nt][2], c[mt][nt][3]);
                *(uint*)(sm + r * 528 + cc * 2)       = *(uint*)&h01;
                *(uint*)(sm + (r + 8) * 528 + cc * 2) = *(uint*)&h23;
            }
        }
        __syncthreads();
        #pragma unroll
        for (int j = 0; j < 8; ++j) {
            int idx = t + 512 * j;          // 0..4095
            int row = idx >> 5, s = idx & 31;
            if (base + row < N) {
                uint4 v = *(uint4*)(sm + row * 528 + s * 16);
                int dst = (s < 16) ? s * 16 : 384 + (s - 16) * 16;
                *(uint4*)&g_proj[(size_t)(base + row) * 768 + dst] = v;
            }
        }
    } else {
        // Stage e4m3, row stride 272 B.
        #pragma unroll
        for (int mt = 0; mt < 2; ++mt) {
            #pragma unroll
            for (int nt = 0; nt < 8; ++nt) {
                int r  = rbase + mt * 16 + lq;
                int cc = cbase + nt * 8 + 2 * lr;
                *(unsigned short*)(sm + r * 272 + cc)       = pack_e4m3_2(c[mt][nt][0], c[mt][nt][1]);
                *(unsigned short*)(sm + (r + 8) * 272 + cc) = pack_e4m3_2(c[mt][nt][2], c[mt][nt][3]);
            }
        }
        __syncthreads();
        #pragma unroll
        for (int j = 0; j < 4; ++j) {
            int idx = t + 512 * j;          // 0..2047
            int row = idx >> 4, s = idx & 15;
            if (base + row < N) {
                uint4 v = *(uint4*)(sm + row * 272 + s * 16);
                int dst = (s < 8) ? 256 + s * 16 : 640 + (s - 8) * 16;
                *(uint4*)&g_proj[(size_t)(base + row) * 768 + dst] = v;
            }
        }
    }
}

// ---------------------------------------------------------------- stage 2 ---
struct S2 {
    __nv_bfloat16 ha[TILE_E][136];   // 17408 B, row stride 272 B
    __nv_bfloat16 A2s[128][72];      // 18432 B, row stride 144 B
    float ab2s[64];
    float pen[TILE_E];
    int   maxsend[TILE_E];
    int   srcs[TILE_E];
    int   tgts[TILE_E];
};

__global__ void __launch_bounds__(256, 5)
edge_kernel(const int*   __restrict__ edges,
            const int*   __restrict__ army,
            const float* __restrict__ b1,
            const float* __restrict__ W2,
            const float* __restrict__ b2,
            const float* __restrict__ ab1,
            const float* __restrict__ ab2,
            float* __restrict__ out,
            int E)
{
    extern __shared__ char smem_raw[];
    S2* S = (S2*)smem_raw;
    const int t = threadIdx.x;
    const int blockBase = blockIdx.x * TILE_E;

    #pragma unroll
    for (int i = 0; i < 4; ++i) {
        int idx = t + 256 * i;               // 0..1023 uint4
        int k = idx >> 3, chunk = idx & 7;
        uint4 v = *(const uint4*)&g_A2[idx * 8];
        *(uint4*)&S->A2s[k][chunk * 8] = v;
    }
    if (t < 64) S->ab2s[t] = ab2[t];
    if (t < TILE_E) {
        int e = blockBase + t;
        int s = 0, g = 0, ms = -1; float pen = 0.f;
        if (e < E) {
            s = __ldcs(&edges[2 * e]); g = __ldcs(&edges[2 * e + 1]);
            int sa = army[s], ta = army[g];
            ms = sa - 1;
            if (sa <= 2 || ta >= 3 * sa) pen += 1.f;
            if (s == g) pen += 100.f;
        }
        S->srcs[t] = s; S->tgts[t] = g; S->maxsend[t] = ms; S->pen[t] = pen;
    }
    __syncthreads();

    const int w = t >> 5, l = t & 31;
    const unsigned char* __restrict__ projc = g_proj;

    float4 b1v  = ((const float4*)b1)[l];
    float4 ab1v = ((const float4*)ab1)[l];
    float4 w2v  = ((const float4*)W2)[l];
    const float b2v = b2[0];

    // Phase 1: 8 warps x 8 edges, full warp per edge, double-buffered gathers.
    const int wbase8 = w * 8;
    uint2 ws[2], wt[2];
    uint  pa[2], pt[2];

    {   // prime buffer 0
        const size_t sB = (size_t)S->srcs[wbase8] * 768;
        const size_t tB = (size_t)S->tgts[wbase8] * 768;
        ws[0] = *(const uint2*)(projc + sB + 8 * l);
        pa[0] = *(const uint*) (projc + sB + 256 + 4 * l);
        wt[0] = *(const uint2*)(projc + tB + 384 + 8 * l);
        pt[0] = *(const uint*) (projc + tB + 640 + 4 * l);
    }

    #pragma unroll
    for (int i = 0; i < 8; ++i) {
        const int cur = i & 1, nxt = cur ^ 1;
        if (i < 7) {
            const size_t sB = (size_t)S->srcs[wbase8 + i + 1] * 768;
            const size_t tB = (size_t)S->tgts[wbase8 + i + 1] * 768;
            ws[nxt] = *(const uint2*)(projc + sB + 8 * l);
            pa[nxt] = *(const uint*) (projc + sB + 256 + 4 * l);
            wt[nxt] = *(const uint2*)(projc + tB + 384 + 8 * l);
            pt[nxt] = *(const uint*) (projc + tB + 640 + 4 * l);
        }
        const int le = wbase8 + i;
        const int e  = blockBase + le;

        // edge head (fp16)
        float2 s01 = __half22float2(*(__half2*)&ws[cur].x);
        float2 s23 = __half22float2(*(__half2*)&ws[cur].y);
        float2 t01 = __half22float2(*(__half2*)&wt[cur].x);
        float2 t23 = __half22float2(*(__half2*)&wt[cur].y);
        float h0 = fmaxf(s01.x + t01.x + b1v.x, 0.f);
        float h1 = fmaxf(s01.y + t01.y + b1v.y, 0.f);
        float h2 = fmaxf(s23.x + t23.x + b1v.z, 0.f);
        float h3 = fmaxf(s23.y + t23.y + b1v.w, 0.f);
        float part = fmaf(h0, w2v.x, fmaf(h1, w2v.y, fmaf(h2, w2v.z, h3 * w2v.w)));
        #pragma unroll
        for (int d = 16; d > 0; d >>= 1)
            part += __shfl_xor_sync(0xffffffffu, part, d);
        if (l == 0 && e < E) __stcs(&out[e], part + b2v - S->pen[le]);

        // army hidden (e4m3 -> fp16 exact -> fp32)
        uint sa01, sa23, ta01, ta23;
        unpack_e4m3_4(pa[cur], sa01, sa23);
        unpack_e4m3_4(pt[cur], ta01, ta23);
        float2 fa0 = __half22float2(*(__half2*)&sa01);
        float2 fa1 = __half22float2(*(__half2*)&sa23);
        float2 ft0 = __half22float2(*(__half2*)&ta01);
        float2 ft1 = __half22float2(*(__half2*)&ta23);
        float g0 = fmaxf(fa0.x + ft0.x + ab1v.x, 0.f);
        float g1 = fmaxf(fa0.y + ft0.y + ab1v.y, 0.f);
        float g2 = fmaxf(fa1.x + ft1.x + ab1v.z, 0.f);
        float g3 = fmaxf(fa1.y + ft1.y + ab1v.w, 0.f);
        __nv_bfloat162 hh0 = __floats2bfloat162_rn(g0, g1);
        __nv_bfloat162 hh1 = __floats2bfloat162_rn(g2, g3);
        uint2 stv; stv.x = *(uint*)&hh0; stv.y = *(uint*)&hh1;
        *(uint2*)&S->ha[le][4 * l] = stv;
    }
    __syncthreads();

    // Phase 2: warp = (m-tile of 16 edges, 32-col half). 8 warps cover 4x2.
    const int mtile   = w >> 1;
    const int cbase   = (w & 1) * 32;
    const int wbase16 = mtile * 16;

    float c[4][4];
    #pragma unroll
    for (int nt = 0; nt < 4; ++nt) {
        float2 ab = *(const float2*)&S->ab2s[cbase + nt * 8 + 2 * (l & 3)];
        c[nt][0] = ab.x; c[nt][1] = ab.y; c[nt][2] = ab.x; c[nt][3] = ab.y;
    }
    unsigned haBase = (unsigned)__cvta_generic_to_shared(&S->ha[0][0]);
    unsigned a2Base = (unsigned)__cvta_generic_to_shared(&S->A2s[0][0]);
    const int m = l >> 3;
    const int arow = wbase16 + (l & 7) + (m & 1) * 8;
    const int akof = (m >> 1) * 8;
    const int bkoff = (l & 7) + (m & 1) * 8;
    const int bnoff = (m >> 1) * 8;

    #pragma unroll
    for (int ks = 0; ks < 8; ++ks) {
        const int k0 = ks * 16;
        unsigned a0, a1, a2, a3;
        unsigned aaddr = haBase + (unsigned)(arow * 272 + (k0 + akof) * 2);
        asm volatile("ldmatrix.sync.aligned.m8n8.x4.shared.b16 {%0,%1,%2,%3}, [%4];"
                     : "=r"(a0), "=r"(a1), "=r"(a2), "=r"(a3) : "r"(aaddr));
        #pragma unroll
        for (int nt2 = 0; nt2 < 2; ++nt2) {
            unsigned b0, b1r, b2r, b3r;
            unsigned baddr = a2Base + (unsigned)((k0 + bkoff) * 144 + (cbase + nt2 * 16 + bnoff) * 2);
            asm volatile("ldmatrix.sync.aligned.m8n8.x4.trans.shared.b16 {%0,%1,%2,%3}, [%4];"
                         : "=r"(b0), "=r"(b1r), "=r"(b2r), "=r"(b3r) : "r"(baddr));
            asm volatile("mma.sync.aligned.m16n8k16.row.col.f32.bf16.bf16.f32 "
                         "{%0,%1,%2,%3},{%4,%5,%6,%7},{%8,%9},{%0,%1,%2,%3};"
                         : "+f"(c[2*nt2][0]), "+f"(c[2*nt2][1]), "+f"(c[2*nt2][2]), "+f"(c[2*nt2][3])
                         : "r"(a0), "r"(a1), "r"(a2), "r"(a3), "r"(b0), "r"(b1r));
            asm volatile("mma.sync.aligned.m16n8k16.row.col.f32.bf16.bf16.f32 "
                         "{%0,%1,%2,%3},{%4,%5,%6,%7},{%8,%9},{%0,%1,%2,%3};"
                         : "+f"(c[2*nt2+1][0]), "+f"(c[2*nt2+1][1]), "+f"(c[2*nt2+1][2]), "+f"(c[2*nt2+1][3])
                         : "r"(a0), "r"(a1), "r"(a2), "r"(a3), "r"(b2r), "r"(b3r));
        }
    }

    // Epilogue: mask + streaming stores.
    const int r0 = wbase16 + (l >> 2);
    const int e0 = blockBase + r0;
    const int e1 = e0 + 8;
    const int ms0 = S->maxsend[r0];
    const int ms1 = S->maxsend[r0 + 8];
    #pragma unroll
    for (int nt = 0; nt < 4; ++nt) {
        const int col = cbase + nt * 8 + 2 * (l & 3);
        if (e0 < E) {
            float2 v;
            v.x = (col     <= ms0) ? c[nt][0] : -1.0e9f;
            v.y = (col + 1 <= ms0) ? c[nt][1] : -1.0e9f;
            __stcs((float2*)&out[(size_t)E + (size_t)e0 * 64 + col], v);
        }
        if (e1 < E) {
            float2 v;
            v.x = (col     <= ms1) ? c[nt][2] : -1.0e9f;
            v.y = (col + 1 <= ms1) ? c[nt][3] : -1.0e9f;
            __stcs((float2*)&out[(size_t)E + (size_t)e1 * 64 + col], v);
        }
    }
}

// ---------------------------------------------------------------- launch ----
extern "C" void kernel_launch(void* const* d_in, const int* in_sizes, int n_in,
                              void* d_out, int out_size)
{
    const float* emb   = (const float*)d_in[0];
    const int*   edges = (const int*)  d_in[1];
    const int*   army  = (const int*)  d_in[2];
    const float* W1    = (const float*)d_in[3];
    const float* b1    = (const float*)d_in[4];
    const float* W2    = (const float*)d_in[5];
    const float* b2    = (const float*)d_in[6];
    const float* A1    = (const float*)d_in[7];
    const float* ab1   = (const float*)d_in[8];
    const float* A2    = (const float*)d_in[9];
    const float* ab2   = (const float*)d_in[10];
    float* out = (float*)d_out;

    int N = in_sizes[0] / 128;
    int E = in_sizes[1] / 2;
    if (N > MAX_N) N = MAX_N;

    a2prep_kernel<<<16, 256>>>(A2);

    cudaFuncSetAttribute(precompute_kernel,
                         cudaFuncAttributeMaxDynamicSharedMemorySize, SM_TOTAL);
    dim3 g1((N + 127) / 128, 2);
    precompute_kernel<<<g1, 512, SM_TOTAL>>>(emb, W1, A1, N);

    cudaFuncSetAttribute(edge_kernel, cudaFuncAttributeMaxDynamicSharedMemorySize,
                         (int)sizeof(S2));
    edge_kernel<<<(E + TILE_E - 1) / TILE_E, 256, sizeof(S2)>>>(
        edges, army, b1, W2, b2, ab1, ab2, out, E);
}

// round 9
// speedup vs baseline: 1.3992x; 1.0296x over previous
#include <cuda_runtime.h>
#include <cuda_bf16.h>
#include <cuda_fp16.h>
#include <cstdint>

typedef unsigned int uint;

#define MAX_N  100000
#define TILE_E 64
#define ITER   4      // edge tiles per block

// Interleaved per-node table, 768 bytes:
//  [0:256)    W src-half: 128 fp16
//  [256:384)  A src-half: 128 e4m3
//  [384:640)  W tgt-half: 128 fp16
//  [640:768)  A tgt-half: 128 e4m3
static __device__ unsigned char g_proj[(size_t)MAX_N * 768];
static __device__ __nv_bfloat16 g_A2[128 * 64];   // A2 pre-converted to bf16

__device__ __forceinline__ uint cvt_tf32(float f) {
    uint r;
    asm("cvt.rna.tf32.f32 %0, %1;" : "=r"(r) : "f"(f));
    return r;
}

__device__ __forceinline__ unsigned short pack_e4m3_2(float f0, float f1) {
    unsigned short r;
    asm("cvt.rn.satfinite.e4m3x2.f32 %0, %2, %1;" : "=h"(r) : "f"(f0), "f"(f1));
    return r;
}

__device__ __forceinline__ void unpack_e4m3_4(uint v, uint& h01, uint& h23) {
    asm("{\n\t.reg .b16 lo, hi;\n\t"
        "mov.b32 {lo, hi}, %2;\n\t"
        "cvt.rn.f16x2.e4m3x2 %0, lo;\n\t"
        "cvt.rn.f16x2.e4m3x2 %1, hi;\n\t}"
        : "=r"(h01), "=r"(h23) : "r"(v));
}

// ------------------------------------------------------------- a2 prep ------
__global__ void __launch_bounds__(256)
a2prep_kernel(const float* __restrict__ A2)
{
    int idx = blockIdx.x * 256 + threadIdx.x;   // 4096 float2 over 16 blocks
    float2 v = ((const float2*)A2)[idx];
    __nv_bfloat162 b = __floats2bfloat162_rn(v.x, v.y);
    *(__nv_bfloat162*)&g_A2[idx * 2] = b;
}

// ---------------------------------------------------------------- stage 1 ---
#define SM_BS_BYTES 135168
#define SM_TOTAL    202752

__global__ void __launch_bounds__(512, 1)
precompute_kernel(const float* __restrict__ emb,
                  const float* __restrict__ W1,
                  const float* __restrict__ A1,
                  int N)
{
    extern __shared__ char sm[];
    uint* Bs = (uint*)sm;                    // [128][264] tf32
    uint* As = (uint*)(sm + SM_BS_BYTES);    // [128][132] tf32

    const int t    = threadIdx.x;
    const int base = blockIdx.x * 128;
    const int isA  = blockIdx.y;
    const float* __restrict__ Wm = isA ? A1 : W1;

    #pragma unroll
    for (int j = 0; j < 16; ++j) {
        int idx  = t + 512 * j;
        int krow = idx >> 5;
        int ch   = idx & 31;
        int koff = (krow >= 128) ? 128 : 0;
        int k    = krow - koff;
        float4 v = *(const float4*)&Wm[(size_t)krow * 128 + 4 * ch];
        uint* dst = &Bs[k * 264 + koff + 4 * ch];
        dst[0] = cvt_tf32(v.x); dst[1] = cvt_tf32(v.y);
        dst[2] = cvt_tf32(v.z); dst[3] = cvt_tf32(v.w);
    }
    #pragma unroll
    for (int j = 0; j < 8; ++j) {
        int idx = t + 512 * j;
        int row = idx >> 5;
        int q   = idx & 31;
        int n   = base + row; if (n >= N) n = N - 1;
        float4 v = ((const float4*)emb)[(size_t)n * 32 + q];
        uint* dst = &As[row * 132 + 4 * q];
        dst[0] = cvt_tf32(v.x); dst[1] = cvt_tf32(v.y);
        dst[2] = cvt_tf32(v.z); dst[3] = cvt_tf32(v.w);
    }
    __syncthreads();

    const int w = t >> 5, l = t & 31;
    const int wm = w >> 2, wn = w & 3;
    const int rbase = wm * 32;
    const int cbase = wn * 64;
    const int lq = l >> 2, lr = l & 3;

    float c[2][8][4];
    #pragma unroll
    for (int mt = 0; mt < 2; ++mt)
        #pragma unroll
        for (int nt = 0; nt < 8; ++nt)
            #pragma unroll
            for (int i = 0; i < 4; ++i) c[mt][nt][i] = 0.f;

    #pragma unroll
    for (int kt = 0; kt < 16; ++kt) {
        const int k0 = kt * 8;
        uint a[2][4];
        #pragma unroll
        for (int mt = 0; mt < 2; ++mt) {
            int r = rbase + mt * 16 + lq;
            a[mt][0] = As[r * 132 + k0 + lr];
            a[mt][1] = As[(r + 8) * 132 + k0 + lr];
            a[mt][2] = As[r * 132 + k0 + 4 + lr];
            a[mt][3] = As[(r + 8) * 132 + k0 + 4 + lr];
        }
        #pragma unroll
        for (int nt = 0; nt < 8; ++nt) {
            uint b0 = Bs[(k0 + lr) * 264 + cbase + nt * 8 + lq];
            uint b1 = Bs[(k0 + 4 + lr) * 264 + cbase + nt * 8 + lq];
            asm volatile("mma.sync.aligned.m16n8k8.row.col.f32.tf32.tf32.f32 "
                         "{%0,%1,%2,%3},{%4,%5,%6,%7},{%8,%9},{%0,%1,%2,%3};"
                         : "+f"(c[0][nt][0]), "+f"(c[0][nt][1]), "+f"(c[0][nt][2]), "+f"(c[0][nt][3])
                         : "r"(a[0][0]), "r"(a[0][1]), "r"(a[0][2]), "r"(a[0][3]),
                           "r"(b0), "r"(b1));
            asm volatile("mma.sync.aligned.m16n8k8.row.col.f32.tf32.tf32.f32 "
                         "{%0,%1,%2,%3},{%4,%5,%6,%7},{%8,%9},{%0,%1,%2,%3};"
                         : "+f"(c[1][nt][0]), "+f"(c[1][nt][1]), "+f"(c[1][nt][2]), "+f"(c[1][nt][3])
                         : "r"(a[1][0]), "r"(a[1][1]), "r"(a[1][2]), "r"(a[1][3]),
                           "r"(b0), "r"(b1));
        }
    }
    __syncthreads();

    if (!isA) {
        #pragma unroll
        for (int mt = 0; mt < 2; ++mt) {
            #pragma unroll
            for (int nt = 0; nt < 8; ++nt) {
                int r  = rbase + mt * 16 + lq;
                int cc = cbase + nt * 8 + 2 * lr;
                __half2 h01 = __floats2half2_rn(c[mt][nt][0], c[mt][nt][1]);
                __half2 h23 = __floats2half2_rn(c[mt][nt][2], c[mt][nt][3]);
                *(uint*)(sm + r * 528 + cc * 2)       = *(uint*)&h01;
                *(uint*)(sm + (r + 8) * 528 + cc * 2) = *(uint*)&h23;
            }
        }
        __syncthreads();
        #pragma unroll
        for (int j = 0; j < 8; ++j) {
            int idx = t + 512 * j;
            int row = idx >> 5, s = idx & 31;
            if (base + row < N) {
                uint4 v = *(uint4*)(sm + row * 528 + s * 16);
                int dst = (s < 16) ? s * 16 : 384 + (s - 16) * 16;
                *(uint4*)&g_proj[(size_t)(base + row) * 768 + dst] = v;
            }
        }
    } else {
        #pragma unroll
        for (int mt = 0; mt < 2; ++mt) {
            #pragma unroll
            for (int nt = 0; nt < 8; ++nt) {
                int r  = rbase + mt * 16 + lq;
                int cc = cbase + nt * 8 + 2 * lr;
                *(unsigned short*)(sm + r * 272 + cc)       = pack_e4m3_2(c[mt][nt][0], c[mt][nt][1]);
                *(unsigned short*)(sm + (r + 8) * 272 + cc) = pack_e4m3_2(c[mt][nt][2], c[mt][nt][3]);
            }
        }
        __syncthreads();
        #pragma unroll
        for (int j = 0; j < 4; ++j) {
            int idx = t + 512 * j;
            int row = idx >> 4, s = idx & 15;
            if (base + row < N) {
                uint4 v = *(uint4*)(sm + row * 272 + s * 16);
                int dst = (s < 8) ? 256 + s * 16 : 640 + (s - 8) * 16;
                *(uint4*)&g_proj[(size_t)(base + row) * 768 + dst] = v;
            }
        }
    }
}

// ---------------------------------------------------------------- stage 2 ---
struct S2 {
    __nv_bfloat16 ha[TILE_E][136];   // 17408 B
    __nv_bfloat16 A2s[128][72];      // 18432 B
    float ab2s[64];
    float pen[TILE_E];
    int   maxsend[TILE_E];
    int   srcs[TILE_E];
    int   tgts[TILE_E];
};

__global__ void __launch_bounds__(256, 5)
edge_kernel(const int*   __restrict__ edges,
            const int*   __restrict__ army,
            const float* __restrict__ b1,
            const float* __restrict__ W2,
            const float* __restrict__ b2,
            const float* __restrict__ ab1,
            const float* __restrict__ ab2,
            float* __restrict__ out,
            int E)
{
    extern __shared__ char smem_raw[];
    S2* S = (S2*)smem_raw;
    const int t = threadIdx.x;

    // Load A2 + ab2 ONCE per block (amortized over ITER tiles).
    #pragma unroll
    for (int i = 0; i < 4; ++i) {
        int idx = t + 256 * i;
        int k = idx >> 3, chunk = idx & 7;
        uint4 v = *(const uint4*)&g_A2[idx * 8];
        *(uint4*)&S->A2s[k][chunk * 8] = v;
    }
    if (t < 64) S->ab2s[t] = ab2[t];

    const int w = t >> 5, l = t & 31;
    const unsigned char* __restrict__ projc = g_proj;

    float4 b1v  = ((const float4*)b1)[l];
    float4 ab1v = ((const float4*)ab1)[l];
    float4 w2v  = ((const float4*)W2)[l];
    const float b2v = b2[0];

    // Phase-2 invariants.
    const int mtile   = w >> 1;
    const int cbase   = (w & 1) * 32;
    const int wbase16 = mtile * 16;
    unsigned haBase = (unsigned)__cvta_generic_to_shared(&S->ha[0][0]);
    unsigned a2Base = (unsigned)__cvta_generic_to_shared(&S->A2s[0][0]);
    const int m = l >> 3;
    const int arow = wbase16 + (l & 7) + (m & 1) * 8;
    const int akof = (m >> 1) * 8;
    const int bkoff = (l & 7) + (m & 1) * 8;
    const int bnoff = (m >> 1) * 8;
    float ab2r[4][2];
    #pragma unroll
    for (int nt = 0; nt < 4; ++nt) {
        float2 ab = *(const float2*)&S->ab2s[cbase + nt * 8 + 2 * (l & 3)];
        ab2r[nt][0] = ab.x; ab2r[nt][1] = ab.y;
    }

    const int wbase8 = w * 8;

    for (int it = 0; it < ITER; ++it) {
        const int blockBase = (blockIdx.x * ITER + it) * TILE_E;

        // Tile metadata.
        if (t < TILE_E) {
            int e = blockBase + t;
            int s = 0, g = 0, ms = -1; float pen = 0.f;
            if (e < E) {
                s = __ldcs(&edges[2 * e]); g = __ldcs(&edges[2 * e + 1]);
                int sa = army[s], ta = army[g];
                ms = sa - 1;
                if (sa <= 2 || ta >= 3 * sa) pen += 1.f;
                if (s == g) pen += 100.f;
            }
            S->srcs[t] = s; S->tgts[t] = g; S->maxsend[t] = ms; S->pen[t] = pen;
        }
        __syncthreads();

        // Phase 1: 8 warps x 8 edges, double-buffered gathers.
        uint2 ws[2], wt[2];
        uint  pa[2], pt[2];
        {
            const size_t sB = (size_t)S->srcs[wbase8] * 768;
            const size_t tB = (size_t)S->tgts[wbase8] * 768;
            ws[0] = *(const uint2*)(projc + sB + 8 * l);
            pa[0] = *(const uint*) (projc + sB + 256 + 4 * l);
            wt[0] = *(const uint2*)(projc + tB + 384 + 8 * l);
            pt[0] = *(const uint*) (projc + tB + 640 + 4 * l);
        }

        #pragma unroll
        for (int i = 0; i < 8; ++i) {
            const int cur = i & 1, nxt = cur ^ 1;
            if (i < 7) {
                const size_t sB = (size_t)S->srcs[wbase8 + i + 1] * 768;
                const size_t tB = (size_t)S->tgts[wbase8 + i + 1] * 768;
                ws[nxt] = *(const uint2*)(projc + sB + 8 * l);
                pa[nxt] = *(const uint*) (projc + sB + 256 + 4 * l);
                wt[nxt] = *(const uint2*)(projc + tB + 384 + 8 * l);
                pt[nxt] = *(const uint*) (projc + tB + 640 + 4 * l);
            }
            const int le = wbase8 + i;
            const int e  = blockBase + le;

            float2 s01 = __half22float2(*(__half2*)&ws[cur].x);
            float2 s23 = __half22float2(*(__half2*)&ws[cur].y);
            float2 t01 = __half22float2(*(__half2*)&wt[cur].x);
            float2 t23 = __half22float2(*(__half2*)&wt[cur].y);
            float h0 = fmaxf(s01.x + t01.x + b1v.x, 0.f);
            float h1 = fmaxf(s01.y + t01.y + b1v.y, 0.f);
            float h2 = fmaxf(s23.x + t23.x + b1v.z, 0.f);
            float h3 = fmaxf(s23.y + t23.y + b1v.w, 0.f);
            float part = fmaf(h0, w2v.x, fmaf(h1, w2v.y, fmaf(h2, w2v.z, h3 * w2v.w)));
            #pragma unroll
            for (int d = 16; d > 0; d >>= 1)
                part += __shfl_xor_sync(0xffffffffu, part, d);
            if (l == 0 && e < E) __stcs(&out[e], part + b2v - S->pen[le]);

            uint sa01, sa23, ta01, ta23;
            unpack_e4m3_4(pa[cur], sa01, sa23);
            unpack_e4m3_4(pt[cur], ta01, ta23);
            float2 fa0 = __half22float2(*(__half2*)&sa01);
            float2 fa1 = __half22float2(*(__half2*)&sa23);
            float2 ft0 = __half22float2(*(__half2*)&ta01);
            float2 ft1 = __half22float2(*(__half2*)&ta23);
            float g0 = fmaxf(fa0.x + ft0.x + ab1v.x, 0.f);
            float g1 = fmaxf(fa0.y + ft0.y + ab1v.y, 0.f);
            float g2 = fmaxf(fa1.x + ft1.x + ab1v.z, 0.f);
            float g3 = fmaxf(fa1.y + ft1.y + ab1v.w, 0.f);
            __nv_bfloat162 hh0 = __floats2bfloat162_rn(g0, g1);
            __nv_bfloat162 hh1 = __floats2bfloat162_rn(g2, g3);
            uint2 stv; stv.x = *(uint*)&hh0; stv.y = *(uint*)&hh1;
            *(uint2*)&S->ha[le][4 * l] = stv;
        }
        __syncthreads();

        // Phase 2: army GEMM.
        float c[4][4];
        #pragma unroll
        for (int nt = 0; nt < 4; ++nt) {
            c[nt][0] = ab2r[nt][0]; c[nt][1] = ab2r[nt][1];
            c[nt][2] = ab2r[nt][0]; c[nt][3] = ab2r[nt][1];
        }

        #pragma unroll
        for (int ks = 0; ks < 8; ++ks) {
            const int k0 = ks * 16;
            unsigned a0, a1, a2, a3;
            unsigned aaddr = haBase + (unsigned)(arow * 272 + (k0 + akof) * 2);
            asm volatile("ldmatrix.sync.aligned.m8n8.x4.shared.b16 {%0,%1,%2,%3}, [%4];"
                         : "=r"(a0), "=r"(a1), "=r"(a2), "=r"(a3) : "r"(aaddr));
            #pragma unroll
            for (int nt2 = 0; nt2 < 2; ++nt2) {
                unsigned b0, b1r, b2r, b3r;
                unsigned baddr = a2Base + (unsigned)((k0 + bkoff) * 144 + (cbase + nt2 * 16 + bnoff) * 2);
                asm volatile("ldmatrix.sync.aligned.m8n8.x4.trans.shared.b16 {%0,%1,%2,%3}, [%4];"
                             : "=r"(b0), "=r"(b1r), "=r"(b2r), "=r"(b3r) : "r"(baddr));
                asm volatile("mma.sync.aligned.m16n8k16.row.col.f32.bf16.bf16.f32 "
                             "{%0,%1,%2,%3},{%4,%5,%6,%7},{%8,%9},{%0,%1,%2,%3};"
                             : "+f"(c[2*nt2][0]), "+f"(c[2*nt2][1]), "+f"(c[2*nt2][2]), "+f"(c[2*nt2][3])
                             : "r"(a0), "r"(a1), "r"(a2), "r"(a3), "r"(b0), "r"(b1r));
                asm volatile("mma.sync.aligned.m16n8k16.row.col.f32.bf16.bf16.f32 "
                             "{%0,%1,%2,%3},{%4,%5,%6,%7},{%8,%9},{%0,%1,%2,%3};"
                             : "+f"(c[2*nt2+1][0]), "+f"(c[2*nt2+1][1]), "+f"(c[2*nt2+1][2]), "+f"(c[2*nt2+1][3])
                             : "r"(a0), "r"(a1), "r"(a2), "r"(a3), "r"(b2r), "r"(b3r));
            }
        }

        // Epilogue.
        const int r0 = wbase16 + (l >> 2);
        const int e0 = blockBase + r0;
        const int e1 = e0 + 8;
        const int ms0 = S->maxsend[r0];
        const int ms1 = S->maxsend[r0 + 8];
        #pragma unroll
        for (int nt = 0; nt < 4; ++nt) {
            const int col = cbase + nt * 8 + 2 * (l & 3);
            if (e0 < E) {
                float2 v;
                v.x = (col     <= ms0) ? c[nt][0] : -1.0e9f;
                v.y = (col + 1 <= ms0) ? c[nt][1] : -1.0e9f;
                __stcs((float2*)&out[(size_t)E + (size_t)e0 * 64 + col], v);
            }
            if (e1 < E) {
                float2 v;
                v.x = (col     <= ms1) ? c[nt][2] : -1.0e9f;
                v.y = (col + 1 <= ms1) ? c[nt][3] : -1.0e9f;
                __stcs((float2*)&out[(size_t)E + (size_t)e1 * 64 + col], v);
            }
        }
        __syncthreads();   // ha reuse barrier for next tile
    }
}

// ---------------------------------------------------------------- launch ----
extern "C" void kernel_launch(void* const* d_in, const int* in_sizes, int n_in,
                              void* d_out, int out_size)
{
    const float* emb   = (const float*)d_in[0];
    const int*   edges = (const int*)  d_in[1];
    const int*   army  = (const int*)  d_in[2];
    const float* W1    = (const float*)d_in[3];
    const float* b1    = (const float*)d_in[4];
    const float* W2    = (const float*)d_in[5];
    const float* b2    = (const float*)d_in[6];
    const float* A1    = (const float*)d_in[7];
    const float* ab1   = (const float*)d_in[8];
    const float* A2    = (const float*)d_in[9];
    const float* ab2   = (const float*)d_in[10];
    float* out = (float*)d_out;

    int N = in_sizes[0] / 128;
    int E = in_sizes[1] / 2;
    if (N > MAX_N) N = MAX_N;

    a2prep_kernel<<<16, 256>>>(A2);

    cudaFuncSetAttribute(precompute_kernel,
                         cudaFuncAttributeMaxDynamicSharedMemorySize, SM_TOTAL);
    dim3 g1((N + 127) / 128, 2);
    precompute_kernel<<<g1, 512, SM_TOTAL>>>(emb, W1, A1, N);

    cudaFuncSetAttribute(edge_kernel, cudaFuncAttributeMaxDynamicSharedMemorySize,
                         (int)sizeof(S2));
    int eblk = (E + TILE_E * ITER - 1) / (TILE_E * ITER);
    edge_kernel<<<eblk, 256, sizeof(S2)>>>(
        edges, army, b1, W2, b2, ab1, ab2, out, E);
}

// round 10
// speedup vs baseline: 1.5139x; 1.0819x over previous
#include <cuda_runtime.h>
#include <cuda_bf16.h>
#include <cuda_fp16.h>
#include <cstdint>

typedef unsigned int uint;

#define MAX_N  100000
#define TILE_E 64
#define ITER   4      // edge tiles per block

// Interleaved per-node table, 768 bytes:
//  [0:256)    W src-half: 128 fp16
//  [256:384)  A src-half: 128 e4m3
//  [384:640)  W tgt-half: 128 fp16
//  [640:768)  A tgt-half: 128 e4m3
static __device__ unsigned char g_proj[(size_t)MAX_N * 768];
static __device__ __nv_bfloat16 g_A2[128 * 64];   // A2 pre-converted to bf16

__device__ __forceinline__ unsigned short pack_e4m3_2(float f0, float f1) {
    unsigned short r;
    asm("cvt.rn.satfinite.e4m3x2.f32 %0, %2, %1;" : "=h"(r) : "f"(f0), "f"(f1));
    return r;
}

__device__ __forceinline__ void unpack_e4m3_4(uint v, uint& h01, uint& h23) {
    asm("{\n\t.reg .b16 lo, hi;\n\t"
        "mov.b32 {lo, hi}, %2;\n\t"
        "cvt.rn.f16x2.e4m3x2 %0, lo;\n\t"
        "cvt.rn.f16x2.e4m3x2 %1, hi;\n\t}"
        : "=r"(h01), "=r"(h23) : "r"(v));
}

// ------------------------------------------------------------- a2 prep ------
__global__ void __launch_bounds__(256)
a2prep_kernel(const float* __restrict__ A2)
{
    int idx = blockIdx.x * 256 + threadIdx.x;   // 4096 float2 over 16 blocks
    float2 v = ((const float2*)A2)[idx];
    __nv_bfloat162 b = __floats2bfloat162_rn(v.x, v.y);
    *(__nv_bfloat162*)&g_A2[idx * 2] = b;
}

// ---------------------------------------------------------------- stage 1 ---
// proj-tile = emb(64 nodes x 128) @ [256-col weight block], fp16 HMMA.
// blockIdx.y = 0: W1 (fp16 out). 1: A1 (e4m3 out).
// smem: WsT [256 cols][272 B] fp16 (B as [n][k], 16B XOR swizzle) = 69632
//       As  [64 rows][272 B]  fp16 (A row-major, no swizzle)      = 17408
#define S1_WS     0
#define S1_AS     69632
#define S1_TOTAL  87040

__global__ void __launch_bounds__(256, 2)
precompute_kernel(const float* __restrict__ emb,
                  const float* __restrict__ W1,
                  const float* __restrict__ A1,
                  int N)
{
    extern __shared__ char sm[];
    char* Ws = sm + S1_WS;
    char* As = sm + S1_AS;

    const int t    = threadIdx.x;
    const int base = blockIdx.x * 64;
    const int isA  = blockIdx.y;
    const float* __restrict__ Wm = isA ? A1 : W1;

    // Load A: 64 nodes x 128 k, fp16 row-major (coalesced writes).
    #pragma unroll
    for (int j = 0; j < 8; ++j) {
        int idx = t + 256 * j;            // 0..2047
        int row = idx >> 5, q = idx & 31;
        int n = base + row; if (n >= N) n = N - 1;
        float4 v = ((const float4*)emb)[(size_t)n * 32 + q];
        __half2 h0 = __floats2half2_rn(v.x, v.y);
        __half2 h1 = __floats2half2_rn(v.z, v.w);
        uint2 st; st.x = *(uint*)&h0; st.y = *(uint*)&h1;
        *(uint2*)(As + row * 272 + q * 8) = st;
    }
    // Load B transposed: WsT[c][k] = (c<128 ? Wm[k][c] : Wm[128+k][c-128]).
    // Pair k-rows so each store is a half2; 16B-granule XOR swizzle on k.
    #pragma unroll
    for (int j = 0; j < 16; ++j) {
        int p = t + 256 * j;              // 0..4095
        int ch = p & 31, kp = p >> 5;     // kp 0..127 (k-row pairs)
        int krow0 = 2 * kp;
        int koff  = (krow0 >= 128) ? 128 : 0;
        int k     = krow0 - koff;         // 0..126 even
        float4 v0 = *(const float4*)&Wm[(size_t)(krow0)     * 128 + 4 * ch];
        float4 v1 = *(const float4*)&Wm[(size_t)(krow0 + 1) * 128 + 4 * ch];
        float a0[4] = {v0.x, v0.y, v0.z, v0.w};
        float a1[4] = {v1.x, v1.y, v1.z, v1.w};
        #pragma unroll
        for (int i = 0; i < 4; ++i) {
            int c = koff + 4 * ch + i;
            __half2 h = __floats2half2_rn(a0[i], a1[i]);
            int byte = (2 * k) ^ (16 * ((c >> 2) & 7));
            *(uint*)(Ws + c * 272 + byte) = *(uint*)&h;
        }
    }
    __syncthreads();

    const int w = t >> 5, l = t & 31;
    const int wm = w >> 2, wn = w & 3;     // 2 m-warps x 4 n-warps
    const int rbase = wm * 32;
    const int cbase = wn * 64;
    const int lq = l >> 2, lr = l & 3;
    const int m  = l >> 3;                 // ldmatrix address role

    unsigned wsBase = (unsigned)__cvta_generic_to_shared(Ws);
    unsigned asBase = (unsigned)__cvta_generic_to_shared(As);

    float c[2][8][4];
    #pragma unroll
    for (int mt = 0; mt < 2; ++mt)
        #pragma unroll
        for (int nt = 0; nt < 8; ++nt)
            #pragma unroll
            for (int i = 0; i < 4; ++i) c[mt][nt][i] = 0.f;

    const int arow_off = (m & 1) * 8 + (l & 7);
    const int aksel    = (m >> 1) * 16;
    const int brow_off = (m >> 1) * 8 + (l & 7);
    const int bksel    = (m & 1) * 16;

    #pragma unroll
    for (int ks = 0; ks < 8; ++ks) {
        uint a[2][4];
        #pragma unroll
        for (int mt = 0; mt < 2; ++mt) {
            int row = rbase + mt * 16 + arow_off;
            unsigned addr = asBase + (unsigned)(row * 272 + ks * 32 + aksel);
            asm volatile("ldmatrix.sync.aligned.m8n8.x4.shared.b16 {%0,%1,%2,%3}, [%4];"
                         : "=r"(a[mt][0]), "=r"(a[mt][1]), "=r"(a[mt][2]), "=r"(a[mt][3])
                         : "r"(addr));
        }
        #pragma unroll
        for (int nt2 = 0; nt2 < 4; ++nt2) {
            int row = cbase + nt2 * 16 + brow_off;
            int byte = (ks * 32 + bksel) ^ (16 * ((row >> 2) & 7));
            unsigned addr = wsBase + (unsigned)(row * 272 + byte);
            uint b0, b1, b2, b3;
            asm volatile("ldmatrix.sync.aligned.m8n8.x4.shared.b16 {%0,%1,%2,%3}, [%4];"
                         : "=r"(b0), "=r"(b1), "=r"(b2), "=r"(b3) : "r"(addr));
            #pragma unroll
            for (int mt = 0; mt < 2; ++mt) {
                asm volatile("mma.sync.aligned.m16n8k16.row.col.f32.f16.f16.f32 "
                             "{%0,%1,%2,%3},{%4,%5,%6,%7},{%8,%9},{%0,%1,%2,%3};"
                             : "+f"(c[mt][2*nt2][0]), "+f"(c[mt][2*nt2][1]),
                               "+f"(c[mt][2*nt2][2]), "+f"(c[mt][2*nt2][3])
                             : "r"(a[mt][0]), "r"(a[mt][1]), "r"(a[mt][2]), "r"(a[mt][3]),
                               "r"(b0), "r"(b1));
                asm volatile("mma.sync.aligned.m16n8k16.row.col.f32.f16.f16.f32 "
                             "{%0,%1,%2,%3},{%4,%5,%6,%7},{%8,%9},{%0,%1,%2,%3};"
                             : "+f"(c[mt][2*nt2+1][0]), "+f"(c[mt][2*nt2+1][1]),
                               "+f"(c[mt][2*nt2+1][2]), "+f"(c[mt][2*nt2+1][3])
                             : "r"(a[mt][0]), "r"(a[mt][1]), "r"(a[mt][2]), "r"(a[mt][3]),
                               "r"(b2), "r"(b3));
            }
        }
    }
    __syncthreads();   // done reading operands; reuse smem for C staging

    if (!isA) {
        // Stage fp16, row stride 528 B (64 rows x 512 B data).
        #pragma unroll
        for (int mt = 0; mt < 2; ++mt) {
            #pragma unroll
            for (int nt = 0; nt < 8; ++nt) {
                int r  = rbase + mt * 16 + lq;
                int cc = cbase + nt * 8 + 2 * lr;
                __half2 h01 = __floats2half2_rn(c[mt][nt][0], c[mt][nt][1]);
                __half2 h23 = __floats2half2_rn(c[mt][nt][2], c[mt][nt][3]);
                *(uint*)(sm + r * 528 + cc * 2)       = *(uint*)&h01;
                *(uint*)(sm + (r + 8) * 528 + cc * 2) = *(uint*)&h23;
            }
        }
        __syncthreads();
        #pragma unroll
        for (int j = 0; j < 8; ++j) {
            int idx = t + 256 * j;           // 0..2047
            int row = idx >> 5, s = idx & 31;
            if (base + row < N) {
                uint4 v = *(uint4*)(sm + row * 528 + s * 16);
                int dst = (s < 16) ? s * 16 : 384 + (s - 16) * 16;
                *(uint4*)&g_proj[(size_t)(base + row) * 768 + dst] = v;
            }
        }
    } else {
        // Stage e4m3, row stride 272 B (64 rows x 256 B data).
        #pragma unroll
        for (int mt = 0; mt < 2; ++mt) {
            #pragma unroll
            for (int nt = 0; nt < 8; ++nt) {
                int r  = rbase + mt * 16 + lq;
                int cc = cbase + nt * 8 + 2 * lr;
                *(unsigned short*)(sm + r * 272 + cc)       = pack_e4m3_2(c[mt][nt][0], c[mt][nt][1]);
                *(unsigned short*)(sm + (r + 8) * 272 + cc) = pack_e4m3_2(c[mt][nt][2], c[mt][nt][3]);
            }
        }
        __syncthreads();
        #pragma unroll
        for (int j = 0; j < 4; ++j) {
            int idx = t + 256 * j;           // 0..1023
            int row = idx >> 4, s = idx & 15;
            if (base + row < N) {
                uint4 v = *(uint4*)(sm + row * 272 + s * 16);
                int dst = (s < 8) ? 256 + s * 16 : 640 + (s - 8) * 16;
                *(uint4*)&g_proj[(size_t)(base + row) * 768 + dst] = v;
            }
        }
    }
}

// ---------------------------------------------------------------- stage 2 ---
struct S2 {
    __nv_bfloat16 ha[TILE_E][136];   // 17408 B
    __nv_bfloat16 A2s[128][72];      // 18432 B
    float ab2s[64];
    float pen[TILE_E];
    int   maxsend[TILE_E];
    int   srcs[TILE_E];
    int   tgts[TILE_E];
};

__global__ void __launch_bounds__(256, 5)
edge_kernel(const int*   __restrict__ edges,
            const int*   __restrict__ army,
            const float* __restrict__ b1,
            const float* __restrict__ W2,
            const float* __restrict__ b2,
            const float* __restrict__ ab1,
            const float* __restrict__ ab2,
            float* __restrict__ out,
            int E)
{
    extern __shared__ char smem_raw[];
    S2* S = (S2*)smem_raw;
    const int t = threadIdx.x;

    // Load A2 + ab2 ONCE per block (amortized over ITER tiles).
    #pragma unroll
    for (int i = 0; i < 4; ++i) {
        int idx = t + 256 * i;
        int k = idx >> 3, chunk = idx & 7;
        uint4 v = *(const uint4*)&g_A2[idx * 8];
        *(uint4*)&S->A2s[k][chunk * 8] = v;
    }
    if (t < 64) S->ab2s[t] = ab2[t];

    const int w = t >> 5, l = t & 31;
    const unsigned char* __restrict__ projc = g_proj;

    float4 b1v  = ((const float4*)b1)[l];
    float4 ab1v = ((const float4*)ab1)[l];
    float4 w2v  = ((const float4*)W2)[l];
    const float b2v = b2[0];

    // Phase-2 invariants.
    const int mtile   = w >> 1;
    const int cbase   = (w & 1) * 32;
    const int wbase16 = mtile * 16;
    unsigned haBase = (unsigned)__cvta_generic_to_shared(&S->ha[0][0]);
    unsigned a2Base = (unsigned)__cvta_generic_to_shared(&S->A2s[0][0]);
    const int m = l >> 3;
    const int arow = wbase16 + (l & 7) + (m & 1) * 8;
    const int akof = (m >> 1) * 8;
    const int bkoff = (l & 7) + (m & 1) * 8;
    const int bnoff = (m >> 1) * 8;
    float ab2r[4][2];
    #pragma unroll
    for (int nt = 0; nt < 4; ++nt) {
        float2 ab = *(const float2*)&S->ab2s[cbase + nt * 8 + 2 * (l & 3)];
        ab2r[nt][0] = ab.x; ab2r[nt][1] = ab.y;
    }

    const int wbase8 = w * 8;

    for (int it = 0; it < ITER; ++it) {
        const int blockBase = (blockIdx.x * ITER + it) * TILE_E;

        if (t < TILE_E) {
            int e = blockBase + t;
            int s = 0, g = 0, ms = -1; float pen = 0.f;
            if (e < E) {
                s = __ldcs(&edges[2 * e]); g = __ldcs(&edges[2 * e + 1]);
                int sa = army[s], ta = army[g];
                ms = sa - 1;
                if (sa <= 2 || ta >= 3 * sa) pen += 1.f;
                if (s == g) pen += 100.f;
            }
            S->srcs[t] = s; S->tgts[t] = g; S->maxsend[t] = ms; S->pen[t] = pen;
        }
        __syncthreads();

        // Phase 1: 8 warps x 8 edges, double-buffered gathers.
        uint2 ws[2], wt[2];
        uint  pa[2], pt[2];
        {
            const size_t sB = (size_t)S->srcs[wbase8] * 768;
            const size_t tB = (size_t)S->tgts[wbase8] * 768;
            ws[0] = *(const uint2*)(projc + sB + 8 * l);
            pa[0] = *(const uint*) (projc + sB + 256 + 4 * l);
            wt[0] = *(const uint2*)(projc + tB + 384 + 8 * l);
            pt[0] = *(const uint*) (projc + tB + 640 + 4 * l);
        }

        #pragma unroll
        for (int i = 0; i < 8; ++i) {
            const int cur = i & 1, nxt = cur ^ 1;
            if (i < 7) {
                const size_t sB = (size_t)S->srcs[wbase8 + i + 1] * 768;
                const size_t tB = (size_t)S->tgts[wbase8 + i + 1] * 768;
                ws[nxt] = *(const uint2*)(projc + sB + 8 * l);
                pa[nxt] = *(const uint*) (projc + sB + 256 + 4 * l);
                wt[nxt] = *(const uint2*)(projc + tB + 384 + 8 * l);
                pt[nxt] = *(const uint*) (projc + tB + 640 + 4 * l);
            }
            const int le = wbase8 + i;
            const int e  = blockBase + le;

            float2 s01 = __half22float2(*(__half2*)&ws[cur].x);
            float2 s23 = __half22float2(*(__half2*)&ws[cur].y);
            float2 t01 = __half22float2(*(__half2*)&wt[cur].x);
            float2 t23 = __half22float2(*(__half2*)&wt[cur].y);
            float h0 = fmaxf(s01.x + t01.x + b1v.x, 0.f);
            float h1 = fmaxf(s01.y + t01.y + b1v.y, 0.f);
            float h2 = fmaxf(s23.x + t23.x + b1v.z, 0.f);
            float h3 = fmaxf(s23.y + t23.y + b1v.w, 0.f);
            float part = fmaf(h0, w2v.x, fmaf(h1, w2v.y, fmaf(h2, w2v.z, h3 * w2v.w)));
            #pragma unroll
            for (int d = 16; d > 0; d >>= 1)
                part += __shfl_xor_sync(0xffffffffu, part, d);
            if (l == 0 && e < E) __stcs(&out[e], part + b2v - S->pen[le]);

            uint sa01, sa23, ta01, ta23;
            unpack_e4m3_4(pa[cur], sa01, sa23);
            unpack_e4m3_4(pt[cur], ta01, ta23);
            float2 fa0 = __half22float2(*(__half2*)&sa01);
            float2 fa1 = __half22float2(*(__half2*)&sa23);
            float2 ft0 = __half22float2(*(__half2*)&ta01);
            float2 ft1 = __half22float2(*(__half2*)&ta23);
            float g0 = fmaxf(fa0.x + ft0.x + ab1v.x, 0.f);
            float g1 = fmaxf(fa0.y + ft0.y + ab1v.y, 0.f);
            float g2 = fmaxf(fa1.x + ft1.x + ab1v.z, 0.f);
            float g3 = fmaxf(fa1.y + ft1.y + ab1v.w, 0.f);
            __nv_bfloat162 hh0 = __floats2bfloat162_rn(g0, g1);
            __nv_bfloat162 hh1 = __floats2bfloat162_rn(g2, g3);
            uint2 stv; stv.x = *(uint*)&hh0; stv.y = *(uint*)&hh1;
            *(uint2*)&S->ha[le][4 * l] = stv;
        }
        __syncthreads();

        // Phase 2: army GEMM.
        float c[4][4];
        #pragma unroll
        for (int nt = 0; nt < 4; ++nt) {
            c[nt][0] = ab2r[nt][0]; c[nt][1] = ab2r[nt][1];
            c[nt][2] = ab2r[nt][0]; c[nt][3] = ab2r[nt][1];
        }

        #pragma unroll
        for (int ks = 0; ks < 8; ++ks) {
            const int k0 = ks * 16;
            unsigned a0, a1, a2, a3;
            unsigned aaddr = haBase + (unsigned)(arow * 272 + (k0 + akof) * 2);
            asm volatile("ldmatrix.sync.aligned.m8n8.x4.shared.b16 {%0,%1,%2,%3}, [%4];"
                         : "=r"(a0), "=r"(a1), "=r"(a2), "=r"(a3) : "r"(aaddr));
            #pragma unroll
            for (int nt2 = 0; nt2 < 2; ++nt2) {
                unsigned b0, b1r, b2r, b3r;
                unsigned baddr = a2Base + (unsigned)((k0 + bkoff) * 144 + (cbase + nt2 * 16 + bnoff) * 2);
                asm volatile("ldmatrix.sync.aligned.m8n8.x4.trans.shared.b16 {%0,%1,%2,%3}, [%4];"
                             : "=r"(b0), "=r"(b1r), "=r"(b2r), "=r"(b3r) : "r"(baddr));
                asm volatile("mma.sync.aligned.m16n8k16.row.col.f32.bf16.bf16.f32 "
                             "{%0,%1,%2,%3},{%4,%5,%6,%7},{%8,%9},{%0,%1,%2,%3};"
                             : "+f"(c[2*nt2][0]), "+f"(c[2*nt2][1]), "+f"(c[2*nt2][2]), "+f"(c[2*nt2][3])
                             : "r"(a0), "r"(a1), "r"(a2), "r"(a3), "r"(b0), "r"(b1r));
                asm volatile("mma.sync.aligned.m16n8k16.row.col.f32.bf16.bf16.f32 "
                             "{%0,%1,%2,%3},{%4,%5,%6,%7},{%8,%9},{%0,%1,%2,%3};"
                             : "+f"(c[2*nt2+1][0]), "+f"(c[2*nt2+1][1]), "+f"(c[2*nt2+1][2]), "+f"(c[2*nt2+1][3])
                             : "r"(a0), "r"(a1), "r"(a2), "r"(a3), "r"(b2r), "r"(b3r));
            }
        }

        // Epilogue.
        const int r0 = wbase16 + (l >> 2);
        const int e0 = blockBase + r0;
        const int e1 = e0 + 8;
        const int ms0 = S->maxsend[r0];
        const int ms1 = S->maxsend[r0 + 8];
        #pragma unroll
        for (int nt = 0; nt < 4; ++nt) {
            const int col = cbase + nt * 8 + 2 * (l & 3);
            if (e0 < E) {
                float2 v;
                v.x = (col     <= ms0) ? c[nt][0] : -1.0e9f;
                v.y = (col + 1 <= ms0) ? c[nt][1] : -1.0e9f;
                __stcs((float2*)&out[(size_t)E + (size_t)e0 * 64 + col], v);
            }
            if (e1 < E) {
                float2 v;
                v.x = (col     <= ms1) ? c[nt][2] : -1.0e9f;
                v.y = (col + 1 <= ms1) ? c[nt][3] : -1.0e9f;
                __stcs((float2*)&out[(size_t)E + (size_t)e1 * 64 + col], v);
            }
        }
        __syncthreads();   // ha reuse barrier for next tile
    }
}

// ---------------------------------------------------------------- launch ----
extern "C" void kernel_launch(void* const* d_in, const int* in_sizes, int n_in,
                              void* d_out, int out_size)
{
    const float* emb   = (const float*)d_in[0];
    const int*   edges = (const int*)  d_in[1];
    const int*   army  = (const int*)  d_in[2];
    const float* W1    = (const float*)d_in[3];
    const float* b1    = (const float*)d_in[4];
    const float* W2    = (const float*)d_in[5];
    const float* b2    = (const float*)d_in[6];
    const float* A1    = (const float*)d_in[7];
    const float* ab1   = (const float*)d_in[8];
    const float* A2    = (const float*)d_in[9];
    const float* ab2   = (const float*)d_in[10];
    float* out = (float*)d_out;

    int N = in_sizes[0] / 128;
    int E = in_sizes[1] / 2;
    if (N > MAX_N) N = MAX_N;

    a2prep_kernel<<<16, 256>>>(A2);

    cudaFuncSetAttribute(precompute_kernel,
                         cudaFuncAttributeMaxDynamicSharedMemorySize, S1_TOTAL);
    dim3 g1((N + 63) / 64, 2);
    precompute_kernel<<<g1, 256, S1_TOTAL>>>(emb, W1, A1, N);

    cudaFuncSetAttribute(edge_kernel, cudaFuncAttributeMaxDynamicSharedMemorySize,
                         (int)sizeof(S2));
    int eblk = (E + TILE_E * ITER - 1) / (TILE_E * ITER);
    edge_kernel<<<eblk, 256, sizeof(S2)>>>(
        edges, army, b1, W2, b2, ab1, ab2, out, E);
}

// round 11
// speedup vs baseline: 1.5306x; 1.0110x over previous
#include <cuda_runtime.h>
#include <cuda_bf16.h>
#include <cuda_fp16.h>
#include <cstdint>

typedef unsigned int uint;

#define MAX_N  100000
#define TILE_E 64
#define ITER   4      // edge tiles per block

// Interleaved per-node table, 768 bytes:
//  [0:256)    W src-half: 128 fp16
//  [256:384)  A src-half: 128 e4m3
//  [384:640)  W tgt-half: 128 fp16
//  [640:768)  A tgt-half: 128 e4m3
static __device__ unsigned char g_proj[(size_t)MAX_N * 768];
static __device__ __half g_A2h[128 * 64];   // A2 pre-converted to fp16

__device__ __forceinline__ unsigned short pack_e4m3_2(float f0, float f1) {
    unsigned short r;
    asm("cvt.rn.satfinite.e4m3x2.f32 %0, %2, %1;" : "=h"(r) : "f"(f0), "f"(f1));
    return r;
}

// unpack uint of 4 e4m3 -> two half2 (exact)
__device__ __forceinline__ void unpack_e4m3_4(uint v, uint& h01, uint& h23) {
    asm("{\n\t.reg .b16 lo, hi;\n\t"
        "mov.b32 {lo, hi}, %2;\n\t"
        "cvt.rn.f16x2.e4m3x2 %0, lo;\n\t"
        "cvt.rn.f16x2.e4m3x2 %1, hi;\n\t}"
        : "=r"(h01), "=r"(h23) : "r"(v));
}

// ------------------------------------------------------------- a2 prep ------
__global__ void __launch_bounds__(256)
a2prep_kernel(const float* __restrict__ A2)
{
    int idx = blockIdx.x * 256 + threadIdx.x;   // 4096 float2 over 16 blocks
    float2 v = ((const float2*)A2)[idx];
    __half2 b = __floats2half2_rn(v.x, v.y);
    *(__half2*)&g_A2h[idx * 2] = b;
}

// ---------------------------------------------------------------- stage 1 ---
// proj-tile = emb(64 nodes x 128) @ [256-col weight block], fp16 HMMA.
// blockIdx.y = 0: W1 (fp16 out). 1: A1 (e4m3 out).
#define S1_WS     0
#define S1_AS     69632
#define S1_TOTAL  87040

__global__ void __launch_bounds__(256, 2)
precompute_kernel(const float* __restrict__ emb,
                  const float* __restrict__ W1,
                  const float* __restrict__ A1,
                  int N)
{
    extern __shared__ char sm[];
    char* Ws = sm + S1_WS;
    char* As = sm + S1_AS;

    const int t    = threadIdx.x;
    const int base = blockIdx.x * 64;
    const int isA  = blockIdx.y;
    const float* __restrict__ Wm = isA ? A1 : W1;

    #pragma unroll
    for (int j = 0; j < 8; ++j) {
        int idx = t + 256 * j;            // 0..2047
        int row = idx >> 5, q = idx & 31;
        int n = base + row; if (n >= N) n = N - 1;
        float4 v = ((const float4*)emb)[(size_t)n * 32 + q];
        __half2 h0 = __floats2half2_rn(v.x, v.y);
        __half2 h1 = __floats2half2_rn(v.z, v.w);
        uint2 st; st.x = *(uint*)&h0; st.y = *(uint*)&h1;
        *(uint2*)(As + row * 272 + q * 8) = st;
    }
    #pragma unroll
    for (int j = 0; j < 16; ++j) {
        int p = t + 256 * j;              // 0..4095
        int ch = p & 31, kp = p >> 5;
        int krow0 = 2 * kp;
        int koff  = (krow0 >= 128) ? 128 : 0;
        int k     = krow0 - koff;
        float4 v0 = *(const float4*)&Wm[(size_t)(krow0)     * 128 + 4 * ch];
        float4 v1 = *(const float4*)&Wm[(size_t)(krow0 + 1) * 128 + 4 * ch];
        float a0[4] = {v0.x, v0.y, v0.z, v0.w};
        float a1[4] = {v1.x, v1.y, v1.z, v1.w};
        #pragma unroll
        for (int i = 0; i < 4; ++i) {
            int c = koff + 4 * ch + i;
            __half2 h = __floats2half2_rn(a0[i], a1[i]);
            int byte = (2 * k) ^ (16 * ((c >> 2) & 7));
            *(uint*)(Ws + c * 272 + byte) = *(uint*)&h;
        }
    }
    __syncthreads();

    const int w = t >> 5, l = t & 31;
    const int wm = w >> 2, wn = w & 3;
    const int rbase = wm * 32;
    const int cbase = wn * 64;
    const int lq = l >> 2, lr = l & 3;
    const int m  = l >> 3;

    unsigned wsBase = (unsigned)__cvta_generic_to_shared(Ws);
    unsigned asBase = (unsigned)__cvta_generic_to_shared(As);

    float c[2][8][4];
    #pragma unroll
    for (int mt = 0; mt < 2; ++mt)
        #pragma unroll
        for (int nt = 0; nt < 8; ++nt)
            #pragma unroll
            for (int i = 0; i < 4; ++i) c[mt][nt][i] = 0.f;

    const int arow_off = (m & 1) * 8 + (l & 7);
    const int aksel    = (m >> 1) * 16;
    const int brow_off = (m >> 1) * 8 + (l & 7);
    const int bksel    = (m & 1) * 16;

    #pragma unroll
    for (int ks = 0; ks < 8; ++ks) {
        uint a[2][4];
        #pragma unroll
        for (int mt = 0; mt < 2; ++mt) {
            int row = rbase + mt * 16 + arow_off;
            unsigned addr = asBase + (unsigned)(row * 272 + ks * 32 + aksel);
            asm volatile("ldmatrix.sync.aligned.m8n8.x4.shared.b16 {%0,%1,%2,%3}, [%4];"
                         : "=r"(a[mt][0]), "=r"(a[mt][1]), "=r"(a[mt][2]), "=r"(a[mt][3])
                         : "r"(addr));
        }
        #pragma unroll
        for (int nt2 = 0; nt2 < 4; ++nt2) {
            int row = cbase + nt2 * 16 + brow_off;
            int byte = (ks * 32 + bksel) ^ (16 * ((row >> 2) & 7));
            unsigned addr = wsBase + (unsigned)(row * 272 + byte);
            uint b0, b1, b2, b3;
            asm volatile("ldmatrix.sync.aligned.m8n8.x4.shared.b16 {%0,%1,%2,%3}, [%4];"
                         : "=r"(b0), "=r"(b1), "=r"(b2), "=r"(b3) : "r"(addr));
            #pragma unroll
            for (int mt = 0; mt < 2; ++mt) {
                asm volatile("mma.sync.aligned.m16n8k16.row.col.f32.f16.f16.f32 "
                             "{%0,%1,%2,%3},{%4,%5,%6,%7},{%8,%9},{%0,%1,%2,%3};"
                             : "+f"(c[mt][2*nt2][0]), "+f"(c[mt][2*nt2][1]),
                               "+f"(c[mt][2*nt2][2]), "+f"(c[mt][2*nt2][3])
                             : "r"(a[mt][0]), "r"(a[mt][1]), "r"(a[mt][2]), "r"(a[mt][3]),
                               "r"(b0), "r"(b1));
                asm volatile("mma.sync.aligned.m16n8k16.row.col.f32.f16.f16.f32 "
                             "{%0,%1,%2,%3},{%4,%5,%6,%7},{%8,%9},{%0,%1,%2,%3};"
                             : "+f"(c[mt][2*nt2+1][0]), "+f"(c[mt][2*nt2+1][1]),
                               "+f"(c[mt][2*nt2+1][2]), "+f"(c[mt][2*nt2+1][3])
                             : "r"(a[mt][0]), "r"(a[mt][1]), "r"(a[mt][2]), "r"(a[mt][3]),
                               "r"(b2), "r"(b3));
            }
        }
    }
    __syncthreads();

    if (!isA) {
        #pragma unroll
        for (int mt = 0; mt < 2; ++mt) {
            #pragma unroll
            for (int nt = 0; nt < 8; ++nt) {
                int r  = rbase + mt * 16 + lq;
                int cc = cbase + nt * 8 + 2 * lr;
                __half2 h01 = __floats2half2_rn(c[mt][nt][0], c[mt][nt][1]);
                __half2 h23 = __floats2half2_rn(c[mt][nt][2], c[mt][nt][3]);
                *(uint*)(sm + r * 528 + cc * 2)       = *(uint*)&h01;
                *(uint*)(sm + (r + 8) * 528 + cc * 2) = *(uint*)&h23;
            }
        }
        __syncthreads();
        #pragma unroll
        for (int j = 0; j < 8; ++j) {
            int idx = t + 256 * j;
            int row = idx >> 5, s = idx & 31;
            if (base + row < N) {
                uint4 v = *(uint4*)(sm + row * 528 + s * 16);
                int dst = (s < 16) ? s * 16 : 384 + (s - 16) * 16;
                *(uint4*)&g_proj[(size_t)(base + row) * 768 + dst] = v;
            }
        }
    } else {
        #pragma unroll
        for (int mt = 0; mt < 2; ++mt) {
            #pragma unroll
            for (int nt = 0; nt < 8; ++nt) {
                int r  = rbase + mt * 16 + lq;
                int cc = cbase + nt * 8 + 2 * lr;
                *(unsigned short*)(sm + r * 272 + cc)       = pack_e4m3_2(c[mt][nt][0], c[mt][nt][1]);
                *(unsigned short*)(sm + (r + 8) * 272 + cc) = pack_e4m3_2(c[mt][nt][2], c[mt][nt][3]);
            }
        }
        __syncthreads();
        #pragma unroll
        for (int j = 0; j < 4; ++j) {
            int idx = t + 256 * j;
            int row = idx >> 4, s = idx & 15;
            if (base + row < N) {
                uint4 v = *(uint4*)(sm + row * 272 + s * 16);
                int dst = (s < 8) ? 256 + s * 16 : 640 + (s - 8) * 16;
                *(uint4*)&g_proj[(size_t)(base + row) * 768 + dst] = v;
            }
        }
    }
}

// ---------------------------------------------------------------- stage 2 ---
struct S2 {
    __half ha[TILE_E][136];    // 17408 B, fp16 hidden
    __half A2s[128][72];       // 18432 B, fp16 weights
    float ab2s[64];
    float pen[TILE_E];
    int   maxsend[TILE_E];
    int   srcs[TILE_E];
    int   tgts[TILE_E];
};

__global__ void __launch_bounds__(256, 5)
edge_kernel(const int*   __restrict__ edges,
            const int*   __restrict__ army,
            const float* __restrict__ b1,
            const float* __restrict__ W2,
            const float* __restrict__ b2,
            const float* __restrict__ ab1,
            const float* __restrict__ ab2,
            float* __restrict__ out,
            int E)
{
    extern __shared__ char smem_raw[];
    S2* S = (S2*)smem_raw;
    const int t = threadIdx.x;

    // A2 (fp16) + ab2 loaded once per block.
    #pragma unroll
    for (int i = 0; i < 4; ++i) {
        int idx = t + 256 * i;
        int k = idx >> 3, chunk = idx & 7;
        uint4 v = *(const uint4*)&g_A2h[idx * 8];
        *(uint4*)&S->A2s[k][chunk * 8] = v;
    }
    if (t < 64) S->ab2s[t] = ab2[t];

    const int w = t >> 5, l = t & 31;
    const unsigned char* __restrict__ projc = g_proj;

    // Half-warp edge assignment: lanes 0-15 edge a, 16-31 edge b.
    const int half = l >> 4;      // 0 or 1
    const int fl   = l & 15;      // feature lane: owns features fl*8 .. fl*8+7
    const int f8   = fl * 8;

    // Per-lane constants as half2 (4 each).
    __half2 b1h[4], ab1h[4], w2h[4];
    {
        float4 xa = ((const float4*)(b1 + f8))[0];
        float4 xb = ((const float4*)(b1 + f8))[1];
        b1h[0] = __floats2half2_rn(xa.x, xa.y); b1h[1] = __floats2half2_rn(xa.z, xa.w);
        b1h[2] = __floats2half2_rn(xb.x, xb.y); b1h[3] = __floats2half2_rn(xb.z, xb.w);
        float4 ya = ((const float4*)(ab1 + f8))[0];
        float4 yb = ((const float4*)(ab1 + f8))[1];
        ab1h[0] = __floats2half2_rn(ya.x, ya.y); ab1h[1] = __floats2half2_rn(ya.z, ya.w);
        ab1h[2] = __floats2half2_rn(yb.x, yb.y); ab1h[3] = __floats2half2_rn(yb.z, yb.w);
        float4 za = ((const float4*)(W2 + f8))[0];
        float4 zb = ((const float4*)(W2 + f8))[1];
        w2h[0] = __floats2half2_rn(za.x, za.y); w2h[1] = __floats2half2_rn(za.z, za.w);
        w2h[2] = __floats2half2_rn(zb.x, zb.y); w2h[3] = __floats2half2_rn(zb.z, zb.w);
    }
    const float b2v = b2[0];
    const __half2 zero2 = __half2half2(__float2half(0.f));

    // Phase-2 invariants.
    const int mtile   = w >> 1;
    const int cbase   = (w & 1) * 32;
    const int wbase16 = mtile * 16;
    unsigned haBase = (unsigned)__cvta_generic_to_shared(&S->ha[0][0]);
    unsigned a2Base = (unsigned)__cvta_generic_to_shared(&S->A2s[0][0]);
    const int m = l >> 3;
    const int arow = wbase16 + (l & 7) + (m & 1) * 8;
    const int akof = (m >> 1) * 8;
    const int bkoff = (l & 7) + (m & 1) * 8;
    const int bnoff = (m >> 1) * 8;
    float ab2r[4][2];
    #pragma unroll
    for (int nt = 0; nt < 4; ++nt) {
        float2 ab = *(const float2*)&S->ab2s[cbase + nt * 8 + 2 * (l & 3)];
        ab2r[nt][0] = ab.x; ab2r[nt][1] = ab.y;
    }

    const int wbase8 = w * 8;

    for (int it = 0; it < ITER; ++it) {
        const int blockBase = (blockIdx.x * ITER + it) * TILE_E;

        if (t < TILE_E) {
            int e = blockBase + t;
            int s = 0, g = 0, ms = -1; float pen = 0.f;
            if (e < E) {
                s = __ldcs(&edges[2 * e]); g = __ldcs(&edges[2 * e + 1]);
                int sa = army[s], ta = army[g];
                ms = sa - 1;
                if (sa <= 2 || ta >= 3 * sa) pen += 1.f;
                if (s == g) pen += 100.f;
            }
            S->srcs[t] = s; S->tgts[t] = g; S->maxsend[t] = ms; S->pen[t] = pen;
        }
        __syncthreads();

        // Phase 1: 4 iterations x 2 edges/warp (lane halves), double-buffered.
        uint4 wsv[2], wtv[2];
        uint2 pav[2], ptv[2];
        {
            const int le = wbase8 + half;
            const size_t sB = (size_t)S->srcs[le] * 768;
            const size_t tB = (size_t)S->tgts[le] * 768;
            wsv[0] = *(const uint4*)(projc + sB + f8 * 2);
            pav[0] = *(const uint2*)(projc + sB + 256 + f8);
            wtv[0] = *(const uint4*)(projc + tB + 384 + f8 * 2);
            ptv[0] = *(const uint2*)(projc + tB + 640 + f8);
        }

        #pragma unroll
        for (int i = 0; i < 4; ++i) {
            const int cur = i & 1, nxt = cur ^ 1;
            if (i < 3) {
                const int le = wbase8 + 2 * (i + 1) + half;
                const size_t sB = (size_t)S->srcs[le] * 768;
                const size_t tB = (size_t)S->tgts[le] * 768;
                wsv[nxt] = *(const uint4*)(projc + sB + f8 * 2);
                pav[nxt] = *(const uint2*)(projc + sB + 256 + f8);
                wtv[nxt] = *(const uint4*)(projc + tB + 384 + f8 * 2);
                ptv[nxt] = *(const uint2*)(projc + tB + 640 + f8);
            }
            const int le = wbase8 + 2 * i + half;
            const int e  = blockBase + le;

            // --- edge head: all half2 ---
            __half2 sw[4], tw[4];
            sw[0] = *(__half2*)&wsv[cur].x; sw[1] = *(__half2*)&wsv[cur].y;
            sw[2] = *(__half2*)&wsv[cur].z; sw[3] = *(__half2*)&wsv[cur].w;
            tw[0] = *(__half2*)&wtv[cur].x; tw[1] = *(__half2*)&wtv[cur].y;
            tw[2] = *(__half2*)&wtv[cur].z; tw[3] = *(__half2*)&wtv[cur].w;
            __half2 acc2 = zero2;
            #pragma unroll
            for (int q = 0; q < 4; ++q) {
                __half2 h = __hmax2(__hadd2(__hadd2(sw[q], tw[q]), b1h[q]), zero2);
                acc2 = __hfma2(h, w2h[q], acc2);
            }
            float2 pf = __half22float2(acc2);
            float part = pf.x + pf.y;
            #pragma unroll
            for (int d = 8; d > 0; d >>= 1)
                part += __shfl_xor_sync(0xffffffffu, part, d);
            if (fl == 0 && e < E) __stcs(&out[e], part + b2v - S->pen[le]);

            // --- army hidden: e4m3 -> half2, all half2 ---
            uint sa01, sa23, sa45, sa67, ta01, ta23, ta45, ta67;
            unpack_e4m3_4(pav[cur].x, sa01, sa23);
            unpack_e4m3_4(pav[cur].y, sa45, sa67);
            unpack_e4m3_4(ptv[cur].x, ta01, ta23);
            unpack_e4m3_4(ptv[cur].y, ta45, ta67);
            __half2 g0 = __hmax2(__hadd2(__hadd2(*(__half2*)&sa01, *(__half2*)&ta01), ab1h[0]), zero2);
            __half2 g1 = __hmax2(__hadd2(__hadd2(*(__half2*)&sa23, *(__half2*)&ta23), ab1h[1]), zero2);
            __half2 g2 = __hmax2(__hadd2(__hadd2(*(__half2*)&sa45, *(__half2*)&ta45), ab1h[2]), zero2);
            __half2 g3 = __hmax2(__hadd2(__hadd2(*(__half2*)&sa67, *(__half2*)&ta67), ab1h[3]), zero2);
            uint4 stv;
            stv.x = *(uint*)&g0; stv.y = *(uint*)&g1;
            stv.z = *(uint*)&g2; stv.w = *(uint*)&g3;
            *(uint4*)&S->ha[le][f8] = stv;
        }
        __syncthreads();

        // Phase 2: army GEMM, fp16 HMMA.
        float c[4][4];
        #pragma unroll
        for (int nt = 0; nt < 4; ++nt) {
            c[nt][0] = ab2r[nt][0]; c[nt][1] = ab2r[nt][1];
            c[nt][2] = ab2r[nt][0]; c[nt][3] = ab2r[nt][1];
        }

        #pragma unroll
        for (int ks = 0; ks < 8; ++ks) {
            const int k0 = ks * 16;
            unsigned a0, a1, a2, a3;
            unsigned aaddr = haBase + (unsigned)(arow * 272 + (k0 + akof) * 2);
            asm volatile("ldmatrix.sync.aligned.m8n8.x4.shared.b16 {%0,%1,%2,%3}, [%4];"
                         : "=r"(a0), "=r"(a1), "=r"(a2), "=r"(a3) : "r"(aaddr));
            #pragma unroll
            for (int nt2 = 0; nt2 < 2; ++nt2) {
                unsigned b0, b1r, b2r, b3r;
                unsigned baddr = a2Base + (unsigned)((k0 + bkoff) * 144 + (cbase + nt2 * 16 + bnoff) * 2);
                asm volatile("ldmatrix.sync.aligned.m8n8.x4.trans.shared.b16 {%0,%1,%2,%3}, [%4];"
                             : "=r"(b0), "=r"(b1r), "=r"(b2r), "=r"(b3r) : "r"(baddr));
                asm volatile("mma.sync.aligned.m16n8k16.row.col.f32.f16.f16.f32 "
                             "{%0,%1,%2,%3},{%4,%5,%6,%7},{%8,%9},{%0,%1,%2,%3};"
                             : "+f"(c[2*nt2][0]), "+f"(c[2*nt2][1]), "+f"(c[2*nt2][2]), "+f"(c[2*nt2][3])
                             : "r"(a0), "r"(a1), "r"(a2), "r"(a3), "r"(b0), "r"(b1r));
                asm volatile("mma.sync.aligned.m16n8k16.row.col.f32.f16.f16.f32 "
                             "{%0,%1,%2,%3},{%4,%5,%6,%7},{%8,%9},{%0,%1,%2,%3};"
                             : "+f"(c[2*nt2+1][0]), "+f"(c[2*nt2+1][1]), "+f"(c[2*nt2+1][2]), "+f"(c[2*nt2+1][3])
                             : "r"(a0), "r"(a1), "r"(a2), "r"(a3), "r"(b2r), "r"(b3r));
            }
        }

        // Epilogue.
        const int r0 = wbase16 + (l >> 2);
        const int e0 = blockBase + r0;
        const int e1 = e0 + 8;
        const int ms0 = S->maxsend[r0];
        const int ms1 = S->maxsend[r0 + 8];
        #pragma unroll
        for (int nt = 0; nt < 4; ++nt) {
            const int col = cbase + nt * 8 + 2 * (l & 3);
            if (e0 < E) {
                float2 v;
                v.x = (col     <= ms0) ? c[nt][0] : -1.0e9f;
                v.y = (col + 1 <= ms0) ? c[nt][1] : -1.0e9f;
                __stcs((float2*)&out[(size_t)E + (size_t)e0 * 64 + col], v);
            }
            if (e1 < E) {
                float2 v;
                v.x = (col     <= ms1) ? c[nt][2] : -1.0e9f;
                v.y = (col + 1 <= ms1) ? c[nt][3] : -1.0e9f;
                __stcs((float2*)&out[(size_t)E + (size_t)e1 * 64 + col], v);
            }
        }
        __syncthreads();
    }
}

// ---------------------------------------------------------------- launch ----
extern "C" void kernel_launch(void* const* d_in, const int* in_sizes, int n_in,
                              void* d_out, int out_size)
{
    const float* emb   = (const float*)d_in[0];
    const int*   edges = (const int*)  d_in[1];
    const int*   army  = (const int*)  d_in[2];
    const float* W1    = (const float*)d_in[3];
    const float* b1    = (const float*)d_in[4];
    const float* W2    = (const float*)d_in[5];
    const float* b2    = (const float*)d_in[6];
    const float* A1    = (const float*)d_in[7];
    const float* ab1   = (const float*)d_in[8];
    const float* A2    = (const float*)d_in[9];
    const float* ab2   = (const float*)d_in[10];
    float* out = (float*)d_out;

    int N = in_sizes[0] / 128;
    int E = in_sizes[1] / 2;
    if (N > MAX_N) N = MAX_N;

    a2prep_kernel<<<16, 256>>>(A2);

    cudaFuncSetAttribute(precompute_kernel,
                         cudaFuncAttributeMaxDynamicSharedMemorySize, S1_TOTAL);
    dim3 g1((N + 63) / 64, 2);
    precompute_kernel<<<g1, 256, S1_TOTAL>>>(emb, W1, A1, N);

    cudaFuncSetAttribute(edge_kernel, cudaFuncAttributeMaxDynamicSharedMemorySize,
                         (int)sizeof(S2));
    int eblk = (E + TILE_E * ITER - 1) / (TILE_E * ITER);
    edge_kernel<<<eblk, 256, sizeof(S2)>>>(
        edges, army, b1, W2, b2, ab1, ab2, out, E);
}

// round 12
// speedup vs baseline: 1.6352x; 1.0684x over previous
#include <cuda_runtime.h>
#include <cuda_bf16.h>
#include <cuda_fp16.h>
#include <cstdint>

typedef unsigned int uint;

#define MAX_N  100000
#define TILE_E 64
#define ITER   8      // edge tiles per block

// Interleaved per-node table, 768 bytes:
//  [0:256)    W src-half: 128 fp16
//  [256:384)  A src-half: 128 e4m3
//  [384:640)  W tgt-half: 128 fp16
//  [640:768)  A tgt-half: 128 e4m3
static __device__ unsigned char g_proj[(size_t)MAX_N * 768];
static __device__ __half g_A2h[128 * 64];            // A2 pre-converted fp16
static __device__ unsigned char g_Wswz[2][256 * 256]; // pre-swizzled fp16 weight images

__device__ __forceinline__ unsigned short pack_e4m3_2(float f0, float f1) {
    unsigned short r;
    asm("cvt.rn.satfinite.e4m3x2.f32 %0, %2, %1;" : "=h"(r) : "f"(f0), "f"(f1));
    return r;
}

__device__ __forceinline__ void unpack_e4m3_4(uint v, uint& h01, uint& h23) {
    asm("{\n\t.reg .b16 lo, hi;\n\t"
        "mov.b32 {lo, hi}, %2;\n\t"
        "cvt.rn.f16x2.e4m3x2 %0, lo;\n\t"
        "cvt.rn.f16x2.e4m3x2 %1, hi;\n\t}"
        : "=r"(h01), "=r"(h23) : "r"(v));
}

// ------------------------------------------------------------- prep ---------
__global__ void __launch_bounds__(256)
a2prep_kernel(const float* __restrict__ A2)
{
    int idx = blockIdx.x * 256 + threadIdx.x;   // 4096 float2 over 16 blocks
    float2 v = ((const float2*)A2)[idx];
    __half2 b = __floats2half2_rn(v.x, v.y);
    *(__half2*)&g_A2h[idx * 2] = b;
}

// Build pre-swizzled fp16 weight images: img 0 = W1, img 1 = A1.
// Image layout: col (0..255) x 256 B; half2(k,k+1) at byte (2k)^(16*((col>>2)&7)).
__global__ void __launch_bounds__(256)
wprep_kernel(const float* __restrict__ W1, const float* __restrict__ A1)
{
    int c = blockIdx.x * 256 + threadIdx.x;   // 0..511
    int img = c >> 8, col = c & 255;
    const float* __restrict__ Wm = img ? A1 : W1;
    int koff = (col >= 128) ? 128 : 0;
    int cc = col - koff;
    unsigned char* dst = g_Wswz[img] + col * 256;
    #pragma unroll 4
    for (int k = 0; k < 128; k += 2) {
        float f0 = Wm[(size_t)(koff + k)     * 128 + cc];
        float f1 = Wm[(size_t)(koff + k + 1) * 128 + cc];
        __half2 h = __floats2half2_rn(f0, f1);
        int byte = (2 * k) ^ (16 * ((col >> 2) & 7));
        *(uint*)(dst + byte) = *(uint*)&h;
    }
}

// ---------------------------------------------------------------- stage 1 ---
// One block = 64 nodes. As loaded ONCE; loop over both weight images.
#define S1_WS     0        // 256 cols x 272 B = 69632
#define S1_AS     69632    // 64 rows x 272 B = 17408
#define S1_TOTAL  87040

__global__ void __launch_bounds__(256, 2)
precompute_kernel(const float* __restrict__ emb, int N)
{
    extern __shared__ char sm[];
    char* Ws = sm + S1_WS;
    char* As = sm + S1_AS;

    const int t    = threadIdx.x;
    const int base = blockIdx.x * 64;

    // Load A: 64 nodes x 128 k, fp32 -> fp16 row-major (once).
    #pragma unroll
    for (int j = 0; j < 8; ++j) {
        int idx = t + 256 * j;            // 0..2047
        int row = idx >> 5, q = idx & 31;
        int n = base + row; if (n >= N) n = N - 1;
        float4 v = ((const float4*)emb)[(size_t)n * 32 + q];
        __half2 h0 = __floats2half2_rn(v.x, v.y);
        __half2 h1 = __floats2half2_rn(v.z, v.w);
        uint2 st; st.x = *(uint*)&h0; st.y = *(uint*)&h1;
        *(uint2*)(As + row * 272 + q * 8) = st;
    }

    const int w = t >> 5, l = t & 31;
    const int wm = w >> 2, wn = w & 3;
    const int rbase = wm * 32;
    const int cbase = wn * 64;
    const int lq = l >> 2, lr = l & 3;
    const int m  = l >> 3;

    unsigned wsBase = (unsigned)__cvta_generic_to_shared(Ws);
    unsigned asBase = (unsigned)__cvta_generic_to_shared(As);

    const int arow_off = (m & 1) * 8 + (l & 7);
    const int aksel    = (m >> 1) * 16;
    const int brow_off = (m >> 1) * 8 + (l & 7);
    const int bksel    = (m & 1) * 16;

    #pragma unroll 1
    for (int img = 0; img < 2; ++img) {
        // Stage Ws: pure byte copy of the pre-swizzled image (4096 uint4).
        __syncthreads();   // prior C-staging reads (img 0) / As writes done
        {
            const unsigned char* src = g_Wswz[img];
            #pragma unroll
            for (int j = 0; j < 16; ++j) {
                int idx = t + 256 * j;            // 0..4095
                int col = idx >> 4, chunk = idx & 15;
                uint4 v = *(const uint4*)(src + col * 256 + chunk * 16);
                *(uint4*)(Ws + col * 272 + chunk * 16) = v;
            }
        }
        __syncthreads();

        float c[2][8][4];
        #pragma unroll
        for (int mt = 0; mt < 2; ++mt)
            #pragma unroll
            for (int nt = 0; nt < 8; ++nt)
                #pragma unroll
                for (int i = 0; i < 4; ++i) c[mt][nt][i] = 0.f;

        #pragma unroll
        for (int ks = 0; ks < 8; ++ks) {
            uint a[2][4];
            #pragma unroll
            for (int mt = 0; mt < 2; ++mt) {
                int row = rbase + mt * 16 + arow_off;
                unsigned addr = asBase + (unsigned)(row * 272 + ks * 32 + aksel);
                asm volatile("ldmatrix.sync.aligned.m8n8.x4.shared.b16 {%0,%1,%2,%3}, [%4];"
                             : "=r"(a[mt][0]), "=r"(a[mt][1]), "=r"(a[mt][2]), "=r"(a[mt][3])
                             : "r"(addr));
            }
            #pragma unroll
            for (int nt2 = 0; nt2 < 4; ++nt2) {
                int row = cbase + nt2 * 16 + brow_off;
                int byte = (ks * 32 + bksel) ^ (16 * ((row >> 2) & 7));
                unsigned addr = wsBase + (unsigned)(row * 272 + byte);
                uint b0, b1, b2, b3;
                asm volatile("ldmatrix.sync.aligned.m8n8.x4.shared.b16 {%0,%1,%2,%3}, [%4];"
                             : "=r"(b0), "=r"(b1), "=r"(b2), "=r"(b3) : "r"(addr));
                #pragma unroll
                for (int mt = 0; mt < 2; ++mt) {
                    asm volatile("mma.sync.aligned.m16n8k16.row.col.f32.f16.f16.f32 "
                                 "{%0,%1,%2,%3},{%4,%5,%6,%7},{%8,%9},{%0,%1,%2,%3};"
                                 : "+f"(c[mt][2*nt2][0]), "+f"(c[mt][2*nt2][1]),
                                   "+f"(c[mt][2*nt2][2]), "+f"(c[mt][2*nt2][3])
                                 : "r"(a[mt][0]), "r"(a[mt][1]), "r"(a[mt][2]), "r"(a[mt][3]),
                                   "r"(b0), "r"(b1));
                    asm volatile("mma.sync.aligned.m16n8k16.row.col.f32.f16.f16.f32 "
                                 "{%0,%1,%2,%3},{%4,%5,%6,%7},{%8,%9},{%0,%1,%2,%3};"
                                 : "+f"(c[mt][2*nt2+1][0]), "+f"(c[mt][2*nt2+1][1]),
                                   "+f"(c[mt][2*nt2+1][2]), "+f"(c[mt][2*nt2+1][3])
                                 : "r"(a[mt][0]), "r"(a[mt][1]), "r"(a[mt][2]), "r"(a[mt][3]),
                                   "r"(b2), "r"(b3));
                }
            }
        }
        __syncthreads();   // done reading Ws; reuse Ws region for C staging

        if (img == 0) {
            // fp16 C staging (row stride 528 B, fits in Ws region) + copy-out.
            #pragma unroll
            for (int mt = 0; mt < 2; ++mt) {
                #pragma unroll
                for (int nt = 0; nt < 8; ++nt) {
                    int r  = rbase + mt * 16 + lq;
                    int cc = cbase + nt * 8 + 2 * lr;
                    __half2 h01 = __floats2half2_rn(c[mt][nt][0], c[mt][nt][1]);
                    __half2 h23 = __floats2half2_rn(c[mt][nt][2], c[mt][nt][3]);
                    *(uint*)(sm + r * 528 + cc * 2)       = *(uint*)&h01;
                    *(uint*)(sm + (r + 8) * 528 + cc * 2) = *(uint*)&h23;
                }
            }
            __syncthreads();
            #pragma unroll
            for (int j = 0; j < 8; ++j) {
                int idx = t + 256 * j;
                int row = idx >> 5, s = idx & 31;
                if (base + row < N) {
                    uint4 v = *(uint4*)(sm + row * 528 + s * 16);
                    int dst = (s < 16) ? s * 16 : 384 + (s - 16) * 16;
                    *(uint4*)&g_proj[(size_t)(base + row) * 768 + dst] = v;
                }
            }
        } else {
            // e4m3 C staging (row stride 272 B) + copy-out.
            #pragma unroll
            for (int mt = 0; mt < 2; ++mt) {
                #pragma unroll
                for (int nt = 0; nt < 8; ++nt) {
                    int r  = rbase + mt * 16 + lq;
                    int cc = cbase + nt * 8 + 2 * lr;
                    *(unsigned short*)(sm + r * 272 + cc)       = pack_e4m3_2(c[mt][nt][0], c[mt][nt][1]);
                    *(unsigned short*)(sm + (r + 8) * 272 + cc) = pack_e4m3_2(c[mt][nt][2], c[mt][nt][3]);
                }
            }
            __syncthreads();
            #pragma unroll
            for (int j = 0; j < 4; ++j) {
                int idx = t + 256 * j;
                int row = idx >> 4, s = idx & 15;
                if (base + row < N) {
                    uint4 v = *(uint4*)(sm + row * 272 + s * 16);
                    int dst = (s < 8) ? 256 + s * 16 : 640 + (s - 8) * 16;
                    *(uint4*)&g_proj[(size_t)(base + row) * 768 + dst] = v;
                }
            }
        }
    }
}

// ---------------------------------------------------------------- stage 2 ---
struct S2 {
    __half ha[TILE_E][136];    // 17408 B, fp16 hidden
    __half A2s[128][72];       // 18432 B, fp16 weights
    float ab2s[64];
    float pen[TILE_E];
    int   maxsend[TILE_E];
    int   srcs[TILE_E];
    int   tgts[TILE_E];
};

__global__ void __launch_bounds__(256, 5)
edge_kernel(const int*   __restrict__ edges,
            const int*   __restrict__ army,
            const float* __restrict__ b1,
            const float* __restrict__ W2,
            const float* __restrict__ b2,
            const float* __restrict__ ab1,
            const float* __restrict__ ab2,
            float* __restrict__ out,
            int E)
{
    extern __shared__ char smem_raw[];
    S2* S = (S2*)smem_raw;
    const int t = threadIdx.x;

    #pragma unroll
    for (int i = 0; i < 4; ++i) {
        int idx = t + 256 * i;
        int k = idx >> 3, chunk = idx & 7;
        uint4 v = *(const uint4*)&g_A2h[idx * 8];
        *(uint4*)&S->A2s[k][chunk * 8] = v;
    }
    if (t < 64) S->ab2s[t] = ab2[t];

    const int w = t >> 5, l = t & 31;
    const unsigned char* __restrict__ projc = g_proj;

    const int half = l >> 4;
    const int fl   = l & 15;
    const int f8   = fl * 8;

    __half2 b1h[4], ab1h[4], w2h[4];
    {
        float4 xa = ((const float4*)(b1 + f8))[0];
        float4 xb = ((const float4*)(b1 + f8))[1];
        b1h[0] = __floats2half2_rn(xa.x, xa.y); b1h[1] = __floats2half2_rn(xa.z, xa.w);
        b1h[2] = __floats2half2_rn(xb.x, xb.y); b1h[3] = __floats2half2_rn(xb.z, xb.w);
        float4 ya = ((const float4*)(ab1 + f8))[0];
        float4 yb = ((const float4*)(ab1 + f8))[1];
        ab1h[0] = __floats2half2_rn(ya.x, ya.y); ab1h[1] = __floats2half2_rn(ya.z, ya.w);
        ab1h[2] = __floats2half2_rn(yb.x, yb.y); ab1h[3] = __floats2half2_rn(yb.z, yb.w);
        float4 za = ((const float4*)(W2 + f8))[0];
        float4 zb = ((const float4*)(W2 + f8))[1];
        w2h[0] = __floats2half2_rn(za.x, za.y); w2h[1] = __floats2half2_rn(za.z, za.w);
        w2h[2] = __floats2half2_rn(zb.x, zb.y); w2h[3] = __floats2half2_rn(zb.z, zb.w);
    }
    const float b2v = b2[0];
    const __half2 zero2 = __half2half2(__float2half(0.f));

    const int mtile   = w >> 1;
    const int cbase   = (w & 1) * 32;
    const int wbase16 = mtile * 16;
    unsigned haBase = (unsigned)__cvta_generic_to_shared(&S->ha[0][0]);
    unsigned a2Base = (unsigned)__cvta_generic_to_shared(&S->A2s[0][0]);
    const int m = l >> 3;
    const int arow = wbase16 + (l & 7) + (m & 1) * 8;
    const int akof = (m >> 1) * 8;
    const int bkoff = (l & 7) + (m & 1) * 8;
    const int bnoff = (m >> 1) * 8;
    float ab2r[4][2];
    #pragma unroll
    for (int nt = 0; nt < 4; ++nt) {
        float2 ab = *(const float2*)&S->ab2s[cbase + nt * 8 + 2 * (l & 3)];
        ab2r[nt][0] = ab.x; ab2r[nt][1] = ab.y;
    }

    const int wbase8 = w * 8;

    for (int it = 0; it < ITER; ++it) {
        const int blockBase = (blockIdx.x * ITER + it) * TILE_E;

        if (t < TILE_E) {
            int e = blockBase + t;
            int s = 0, g = 0, ms = -1; float pen = 0.f;
            if (e < E) {
                s = __ldcs(&edges[2 * e]); g = __ldcs(&edges[2 * e + 1]);
                int sa = army[s], ta = army[g];
                ms = sa - 1;
                if (sa <= 2 || ta >= 3 * sa) pen += 1.f;
                if (s == g) pen += 100.f;
            }
            S->srcs[t] = s; S->tgts[t] = g; S->maxsend[t] = ms; S->pen[t] = pen;
        }
        __syncthreads();

        // Phase 1: 4 iterations x 2 edges/warp (lane halves), double-buffered.
        uint4 wsv[2], wtv[2];
        uint2 pav[2], ptv[2];
        {
            const int le = wbase8 + half;
            const size_t sB = (size_t)S->srcs[le] * 768;
            const size_t tB = (size_t)S->tgts[le] * 768;
            wsv[0] = *(const uint4*)(projc + sB + f8 * 2);
            pav[0] = *(const uint2*)(projc + sB + 256 + f8);
            wtv[0] = *(const uint4*)(projc + tB + 384 + f8 * 2);
            ptv[0] = *(const uint2*)(projc + tB + 640 + f8);
        }

        #pragma unroll
        for (int i = 0; i < 4; ++i) {
            const int cur = i & 1, nxt = cur ^ 1;
            if (i < 3) {
                const int le = wbase8 + 2 * (i + 1) + half;
                const size_t sB = (size_t)S->srcs[le] * 768;
                const size_t tB = (size_t)S->tgts[le] * 768;
                wsv[nxt] = *(const uint4*)(projc + sB + f8 * 2);
                pav[nxt] = *(const uint2*)(projc + sB + 256 + f8);
                wtv[nxt] = *(const uint4*)(projc + tB + 384 + f8 * 2);
                ptv[nxt] = *(const uint2*)(projc + tB + 640 + f8);
            }
            const int le = wbase8 + 2 * i + half;
            const int e  = blockBase + le;

            __half2 sw[4], tw[4];
            sw[0] = *(__half2*)&wsv[cur].x; sw[1] = *(__half2*)&wsv[cur].y;
            sw[2] = *(__half2*)&wsv[cur].z; sw[3] = *(__half2*)&wsv[cur].w;
            tw[0] = *(__half2*)&wtv[cur].x; tw[1] = *(__half2*)&wtv[cur].y;
            tw[2] = *(__half2*)&wtv[cur].z; tw[3] = *(__half2*)&wtv[cur].w;
            __half2 acc2 = zero2;
            #pragma unroll
            for (int q = 0; q < 4; ++q) {
                __half2 h = __hmax2(__hadd2(__hadd2(sw[q], tw[q]), b1h[q]), zero2);
                acc2 = __hfma2(h, w2h[q], acc2);
            }
            float2 pf = __half22float2(acc2);
            float part = pf.x + pf.y;
            #pragma unroll
            for (int d = 8; d > 0; d >>= 1)
                part += __shfl_xor_sync(0xffffffffu, part, d);
            if (fl == 0 && e < E) __stcs(&out[e], part + b2v - S->pen[le]);

            uint sa01, sa23, sa45, sa67, ta01, ta23, ta45, ta67;
            unpack_e4m3_4(pav[cur].x, sa01, sa23);
            unpack_e4m3_4(pav[cur].y, sa45, sa67);
            unpack_e4m3_4(ptv[cur].x, ta01, ta23);
            unpack_e4m3_4(ptv[cur].y, ta45, ta67);
            __half2 g0 = __hmax2(__hadd2(__hadd2(*(__half2*)&sa01, *(__half2*)&ta01), ab1h[0]), zero2);
            __half2 g1 = __hmax2(__hadd2(__hadd2(*(__half2*)&sa23, *(__half2*)&ta23), ab1h[1]), zero2);
            __half2 g2 = __hmax2(__hadd2(__hadd2(*(__half2*)&sa45, *(__half2*)&ta45), ab1h[2]), zero2);
            __half2 g3 = __hmax2(__hadd2(__hadd2(*(__half2*)&sa67, *(__half2*)&ta67), ab1h[3]), zero2);
            uint4 stv;
            stv.x = *(uint*)&g0; stv.y = *(uint*)&g1;
            stv.z = *(uint*)&g2; stv.w = *(uint*)&g3;
            *(uint4*)&S->ha[le][f8] = stv;
        }
        __syncthreads();

        // Phase 2: army GEMM, fp16 HMMA.
        float c[4][4];
        #pragma unroll
        for (int nt = 0; nt < 4; ++nt) {
            c[nt][0] = ab2r[nt][0]; c[nt][1] = ab2r[nt][1];
            c[nt][2] = ab2r[nt][0]; c[nt][3] = ab2r[nt][1];
        }

        #pragma unroll
        for (int ks = 0; ks < 8; ++ks) {
            const int k0 = ks * 16;
            unsigned a0, a1, a2, a3;
            unsigned aaddr = haBase + (unsigned)(arow * 272 + (k0 + akof) * 2);
            asm volatile("ldmatrix.sync.aligned.m8n8.x4.shared.b16 {%0,%1,%2,%3}, [%4];"
                         : "=r"(a0), "=r"(a1), "=r"(a2), "=r"(a3) : "r"(aaddr));
            #pragma unroll
            for (int nt2 = 0; nt2 < 2; ++nt2) {
                unsigned b0, b1r, b2r, b3r;
                unsigned baddr = a2Base + (unsigned)((k0 + bkoff) * 144 + (cbase + nt2 * 16 + bnoff) * 2);
                asm volatile("ldmatrix.sync.aligned.m8n8.x4.trans.shared.b16 {%0,%1,%2,%3}, [%4];"
                             : "=r"(b0), "=r"(b1r), "=r"(b2r), "=r"(b3r) : "r"(baddr));
                asm volatile("mma.sync.aligned.m16n8k16.row.col.f32.f16.f16.f32 "
                             "{%0,%1,%2,%3},{%4,%5,%6,%7},{%8,%9},{%0,%1,%2,%3};"
                             : "+f"(c[2*nt2][0]), "+f"(c[2*nt2][1]), "+f"(c[2*nt2][2]), "+f"(c[2*nt2][3])
                             : "r"(a0), "r"(a1), "r"(a2), "r"(a3), "r"(b0), "r"(b1r));
                asm volatile("mma.sync.aligned.m16n8k16.row.col.f32.f16.f16.f32 "
                             "{%0,%1,%2,%3},{%4,%5,%6,%7},{%8,%9},{%0,%1,%2,%3};"
                             : "+f"(c[2*nt2+1][0]), "+f"(c[2*nt2+1][1]), "+f"(c[2*nt2+1][2]), "+f"(c[2*nt2+1][3])
                             : "r"(a0), "r"(a1), "r"(a2), "r"(a3), "r"(b2r), "r"(b3r));
            }
        }

        // Epilogue.
        const int r0 = wbase16 + (l >> 2);
        const int e0 = blockBase + r0;
        const int e1 = e0 + 8;
        const int ms0 = S->maxsend[r0];
        const int ms1 = S->maxsend[r0 + 8];
        #pragma unroll
        for (int nt = 0; nt < 4; ++nt) {
            const int col = cbase + nt * 8 + 2 * (l & 3);
            if (e0 < E) {
                float2 v;
                v.x = (col     <= ms0) ? c[nt][0] : -1.0e9f;
                v.y = (col + 1 <= ms0) ? c[nt][1] : -1.0e9f;
                __stcs((float2*)&out[(size_t)E + (size_t)e0 * 64 + col], v);
            }
            if (e1 < E) {
                float2 v;
                v.x = (col     <= ms1) ? c[nt][2] : -1.0e9f;
                v.y = (col + 1 <= ms1) ? c[nt][3] : -1.0e9f;
                __stcs((float2*)&out[(size_t)E + (size_t)e1 * 64 + col], v);
            }
        }
        __syncthreads();
    }
}

// ---------------------------------------------------------------- launch ----
extern "C" void kernel_launch(void* const* d_in, const int* in_sizes, int n_in,
                              void* d_out, int out_size)
{
    const float* emb   = (const float*)d_in[0];
    const int*   edges = (const int*)  d_in[1];
    const int*   army  = (const int*)  d_in[2];
    const float* W1    = (const float*)d_in[3];
    const float* b1    = (const float*)d_in[4];
    const float* W2    = (const float*)d_in[5];
    const float* b2    = (const float*)d_in[6];
    const float* A1    = (const float*)d_in[7];
    const float* ab1   = (const float*)d_in[8];
    const float* A2    = (const float*)d_in[9];
    const float* ab2   = (const float*)d_in[10];
    float* out = (float*)d_out;

    int N = in_sizes[0] / 128;
    int E = in_sizes[1] / 2;
    if (N > MAX_N) N = MAX_N;

    a2prep_kernel<<<16, 256>>>(A2);
    wprep_kernel<<<2, 256>>>(W1, A1);

    cudaFuncSetAttribute(precompute_kernel,
                         cudaFuncAttributeMaxDynamicSharedMemorySize, S1_TOTAL);
    precompute_kernel<<<(N + 63) / 64, 256, S1_TOTAL>>>(emb, N);

    cudaFuncSetAttribute(edge_kernel, cudaFuncAttributeMaxDynamicSharedMemorySize,
                         (int)sizeof(S2));
    int eblk = (E + TILE_E * ITER - 1) / (TILE_E * ITER);
    edge_kernel<<<eblk, 256, sizeof(S2)>>>(
        edges, army, b1, W2, b2, ab1, ab2, out, E);
}

// round 14
// speedup vs baseline: 1.6717x; 1.0223x over previous
#include <cuda_runtime.h>
#include <cuda_bf16.h>
#include <cuda_fp16.h>
#include <cstdint>

typedef unsigned int uint;

#define MAX_N  100000
#define TILE_E 64
#define ITER   8      // edge tiles per block

// Interleaved per-node table, 768 bytes:
//  [0:256)    W src-half: 128 fp16
//  [256:384)  A src-half: 128 e4m3
//  [384:640)  W tgt-half: 128 fp16
//  [640:768)  A tgt-half: 128 e4m3
static __device__ unsigned char g_proj[(size_t)MAX_N * 768];
static __device__ unsigned char g_A2f8[64 * 128];     // A2^T as [n][k] e4m3
static __device__ float         g_ab2[64];
static __device__ unsigned char g_Wswz[2][256 * 256]; // pre-swizzled fp16 weight images

__device__ __forceinline__ unsigned short pack_e4m3_2(float f0, float f1) {
    unsigned short r;
    asm("cvt.rn.satfinite.e4m3x2.f32 %0, %2, %1;" : "=h"(r) : "f"(f0), "f"(f1));
    return r;
}

__device__ __forceinline__ unsigned short cvt_f16x2_e4m3x2(uint h2) {
    unsigned short r;
    asm("cvt.rn.satfinite.e4m3x2.f16x2 %0, %1;" : "=h"(r) : "r"(h2));
    return r;
}

__device__ __forceinline__ void unpack_e4m3_4(uint v, uint& h01, uint& h23) {
    asm("{\n\t.reg .b16 lo, hi;\n\t"
        "mov.b32 {lo, hi}, %2;\n\t"
        "cvt.rn.f16x2.e4m3x2 %0, lo;\n\t"
        "cvt.rn.f16x2.e4m3x2 %1, hi;\n\t}"
        : "=r"(h01), "=r"(h23) : "r"(v));
}

// ------------------------------------------------------------- prep ---------
// A2 (128 x 64 fp32, k-major) -> g_A2f8 [n][k] e4m3; also stash ab2.
__global__ void __launch_bounds__(256)
a2prep_kernel(const float* __restrict__ A2, const float* __restrict__ ab2)
{
    const int t = threadIdx.x;
    const int n = t >> 2, kc = t & 3;       // 64 cols x 4 k-chunks
    #pragma unroll
    for (int j = 0; j < 8; ++j) {
        int k = kc * 32 + j * 4;
        float f0 = A2[(size_t)(k + 0) * 64 + n];
        float f1 = A2[(size_t)(k + 1) * 64 + n];
        float f2 = A2[(size_t)(k + 2) * 64 + n];
        float f3 = A2[(size_t)(k + 3) * 64 + n];
        unsigned short lo = pack_e4m3_2(f0, f1);
        unsigned short hi = pack_e4m3_2(f2, f3);
        uint v;
        asm("mov.b32 %0, {%1, %2};" : "=r"(v) : "h"(lo), "h"(hi));
        *(uint*)&g_A2f8[n * 128 + k] = v;
    }
    if (t < 64) g_ab2[t] = ab2[t];
}

// Build pre-swizzled fp16 weight images: img 0 = W1, img 1 = A1.
__global__ void __launch_bounds__(256)
wprep_kernel(const float* __restrict__ W1, const float* __restrict__ A1)
{
    int c = blockIdx.x * 256 + threadIdx.x;   // 0..511
    int img = c >> 8, col = c & 255;
    const float* __restrict__ Wm = img ? A1 : W1;
    int koff = (col >= 128) ? 128 : 0;
    int cc = col - koff;
    unsigned char* dst = g_Wswz[img] + col * 256;
    #pragma unroll 4
    for (int k = 0; k < 128; k += 2) {
        float f0 = Wm[(size_t)(koff + k)     * 128 + cc];
        float f1 = Wm[(size_t)(koff + k + 1) * 128 + cc];
        __half2 h = __floats2half2_rn(f0, f1);
        int byte = (2 * k) ^ (16 * ((col >> 2) & 7));
        *(uint*)(dst + byte) = *(uint*)&h;
    }
}

// ---------------------------------------------------------------- stage 1 ---
#define S1_WS     0        // 256 cols x 272 B = 69632
#define S1_AS     69632    // 64 rows x 272 B = 17408
#define S1_TOTAL  87040

__global__ void __launch_bounds__(256, 2)
precompute_kernel(const float* __restrict__ emb, int N)
{
    extern __shared__ char sm[];
    char* Ws = sm + S1_WS;
    char* As = sm + S1_AS;

    const int t    = threadIdx.x;
    const int base = blockIdx.x * 64;

    #pragma unroll
    for (int j = 0; j < 8; ++j) {
        int idx = t + 256 * j;
        int row = idx >> 5, q = idx & 31;
        int n = base + row; if (n >= N) n = N - 1;
        float4 v = ((const float4*)emb)[(size_t)n * 32 + q];
        __half2 h0 = __floats2half2_rn(v.x, v.y);
        __half2 h1 = __floats2half2_rn(v.z, v.w);
        uint2 st; st.x = *(uint*)&h0; st.y = *(uint*)&h1;
        *(uint2*)(As + row * 272 + q * 8) = st;
    }

    const int w = t >> 5, l = t & 31;
    const int wm = w >> 2, wn = w & 3;
    const int rbase = wm * 32;
    const int cbase = wn * 64;
    const int lq = l >> 2, lr = l & 3;
    const int m  = l >> 3;

    unsigned wsBase = (unsigned)__cvta_generic_to_shared(Ws);
    unsigned asBase = (unsigned)__cvta_generic_to_shared(As);

    const int arow_off = (m & 1) * 8 + (l & 7);
    const int aksel    = (m >> 1) * 16;
    const int brow_off = (m >> 1) * 8 + (l & 7);
    const int bksel    = (m & 1) * 16;

    #pragma unroll 1
    for (int img = 0; img < 2; ++img) {
        __syncthreads();
        {
            const unsigned char* src = g_Wswz[img];
            #pragma unroll
            for (int j = 0; j < 16; ++j) {
                int idx = t + 256 * j;
                int col = idx >> 4, chunk = idx & 15;
                uint4 v = *(const uint4*)(src + col * 256 + chunk * 16);
                *(uint4*)(Ws + col * 272 + chunk * 16) = v;
            }
        }
        __syncthreads();

        float c[2][8][4];
        #pragma unroll
        for (int mt = 0; mt < 2; ++mt)
            #pragma unroll
            for (int nt = 0; nt < 8; ++nt)
                #pragma unroll
                for (int i = 0; i < 4; ++i) c[mt][nt][i] = 0.f;

        #pragma unroll
        for (int ks = 0; ks < 8; ++ks) {
            uint a[2][4];
            #pragma unroll
            for (int mt = 0; mt < 2; ++mt) {
                int row = rbase + mt * 16 + arow_off;
                unsigned addr = asBase + (unsigned)(row * 272 + ks * 32 + aksel);
                asm volatile("ldmatrix.sync.aligned.m8n8.x4.shared.b16 {%0,%1,%2,%3}, [%4];"
                             : "=r"(a[mt][0]), "=r"(a[mt][1]), "=r"(a[mt][2]), "=r"(a[mt][3])
                             : "r"(addr));
            }
            #pragma unroll
            for (int nt2 = 0; nt2 < 4; ++nt2) {
                int row = cbase + nt2 * 16 + brow_off;
                int byte = (ks * 32 + bksel) ^ (16 * ((row >> 2) & 7));
                unsigned addr = wsBase + (unsigned)(row * 272 + byte);
                uint b0, b1, b2, b3;
                asm volatile("ldmatrix.sync.aligned.m8n8.x4.shared.b16 {%0,%1,%2,%3}, [%4];"
                             : "=r"(b0), "=r"(b1), "=r"(b2), "=r"(b3) : "r"(addr));
                #pragma unroll
                for (int mt = 0; mt < 2; ++mt) {
                    asm volatile("mma.sync.aligned.m16n8k16.row.col.f32.f16.f16.f32 "
                                 "{%0,%1,%2,%3},{%4,%5,%6,%7},{%8,%9},{%0,%1,%2,%3};"
                                 : "+f"(c[mt][2*nt2][0]), "+f"(c[mt][2*nt2][1]),
                                   "+f"(c[mt][2*nt2][2]), "+f"(c[mt][2*nt2][3])
                                 : "r"(a[mt][0]), "r"(a[mt][1]), "r"(a[mt][2]), "r"(a[mt][3]),
                                   "r"(b0), "r"(b1));
                    asm volatile("mma.sync.aligned.m16n8k16.row.col.f32.f16.f16.f32 "
                                 "{%0,%1,%2,%3},{%4,%5,%6,%7},{%8,%9},{%0,%1,%2,%3};"
                                 : "+f"(c[mt][2*nt2+1][0]), "+f"(c[mt][2*nt2+1][1]),
                                   "+f"(c[mt][2*nt2+1][2]), "+f"(c[mt][2*nt2+1][3])
                                 : "r"(a[mt][0]), "r"(a[mt][1]), "r"(a[mt][2]), "r"(a[mt][3]),
                                   "r"(b2), "r"(b3));
                }
            }
        }
        __syncthreads();

        if (img == 0) {
            #pragma unroll
            for (int mt = 0; mt < 2; ++mt) {
                #pragma unroll
                for (int nt = 0; nt < 8; ++nt) {
                    int r  = rbase + mt * 16 + lq;
                    int cc = cbase + nt * 8 + 2 * lr;
                    __half2 h01 = __floats2half2_rn(c[mt][nt][0], c[mt][nt][1]);
                    __half2 h23 = __floats2half2_rn(c[mt][nt][2], c[mt][nt][3]);
                    *(uint*)(sm + r * 528 + cc * 2)       = *(uint*)&h01;
                    *(uint*)(sm + (r + 8) * 528 + cc * 2) = *(uint*)&h23;
                }
            }
            __syncthreads();
            #pragma unroll
            for (int j = 0; j < 8; ++j) {
                int idx = t + 256 * j;
                int row = idx >> 5, s = idx & 31;
                if (base + row < N) {
                    uint4 v = *(uint4*)(sm + row * 528 + s * 16);
                    int dst = (s < 16) ? s * 16 : 384 + (s - 16) * 16;
                    *(uint4*)&g_proj[(size_t)(base + row) * 768 + dst] = v;
                }
            }
        } else {
            #pragma unroll
            for (int mt = 0; mt < 2; ++mt) {
                #pragma unroll
                for (int nt = 0; nt < 8; ++nt) {
                    int r  = rbase + mt * 16 + lq;
                    int cc = cbase + nt * 8 + 2 * lr;
                    *(unsigned short*)(sm + r * 272 + cc)       = pack_e4m3_2(c[mt][nt][0], c[mt][nt][1]);
                    *(unsigned short*)(sm + (r + 8) * 272 + cc) = pack_e4m3_2(c[mt][nt][2], c[mt][nt][3]);
                }
            }
            __syncthreads();
            #pragma unroll
            for (int j = 0; j < 4; ++j) {
                int idx = t + 256 * j;
                int row = idx >> 4, s = idx & 15;
                if (base + row < N) {
                    uint4 v = *(uint4*)(sm + row * 272 + s * 16);
                    int dst = (s < 8) ? 256 + s * 16 : 640 + (s - 8) * 16;
                    *(uint4*)&g_proj[(size_t)(base + row) * 768 + dst] = v;
                }
            }
        }
    }
}

// ---------------------------------------------------------------- stage 2 ---
struct S2 {
    unsigned char ha[TILE_E][144];   // 9216 B, e4m3 hidden
    unsigned char A2s[64][144];      // 9216 B, e4m3 A2^T [n][k]
    float ab2s[64];
    float pen[TILE_E];
    int   maxsend[TILE_E];
    int   srcs[TILE_E];
    int   tgts[TILE_E];
};

__global__ void __launch_bounds__(256, 5)
edge_kernel(const int*   __restrict__ edges,
            const int*   __restrict__ army,
            const float* __restrict__ b1,
            const float* __restrict__ W2,
            const float* __restrict__ b2,
            const float* __restrict__ ab1,
            float* __restrict__ out,
            int E)
{
    extern __shared__ char smem_raw[];
    S2* S = (S2*)smem_raw;
    const int t = threadIdx.x;

    // A2 (e4m3 [n][k]) + ab2 loaded once per block.
    #pragma unroll
    for (int i = 0; i < 2; ++i) {
        int idx = t + 256 * i;               // 0..511: col = idx>>3, 16B chunk
        int col = idx >> 3, chunk = idx & 7;
        uint4 v = *(const uint4*)&g_A2f8[col * 128 + chunk * 16];
        *(uint4*)&S->A2s[col][chunk * 16] = v;
    }
    if (t < 64) S->ab2s[t] = g_ab2[t];

    const int w = t >> 5, l = t & 31;
    const unsigned char* __restrict__ projc = g_proj;

    const int half = l >> 4;
    const int fl   = l & 15;
    const int f8   = fl * 8;

    __half2 b1h[4], ab1h[4], w2h[4];
    {
        float4 xa = ((const float4*)(b1 + f8))[0];
        float4 xb = ((const float4*)(b1 + f8))[1];
        b1h[0] = __floats2half2_rn(xa.x, xa.y); b1h[1] = __floats2half2_rn(xa.z, xa.w);
        b1h[2] = __floats2half2_rn(xb.x, xb.y); b1h[3] = __floats2half2_rn(xb.z, xb.w);
        float4 ya = ((const float4*)(ab1 + f8))[0];
        float4 yb = ((const float4*)(ab1 + f8))[1];
        ab1h[0] = __floats2half2_rn(ya.x, ya.y); ab1h[1] = __floats2half2_rn(ya.z, ya.w);
        ab1h[2] = __floats2half2_rn(yb.x, yb.y); ab1h[3] = __floats2half2_rn(yb.z, yb.w);
        float4 za = ((const float4*)(W2 + f8))[0];
        float4 zb = ((const float4*)(W2 + f8))[1];
        w2h[0] = __floats2half2_rn(za.x, za.y); w2h[1] = __floats2half2_rn(za.z, za.w);
        w2h[2] = __floats2half2_rn(zb.x, zb.y); w2h[3] = __floats2half2_rn(zb.z, zb.w);
    }
    const float b2v = b2[0];
    const __half2 zero2 = __half2half2(__float2half(0.f));

    __syncthreads();   // A2s/ab2s visible before first use

    // Phase-2 invariants (fp8 m16n8k32).
    const int mtile   = w >> 1;
    const int cbase   = (w & 1) * 32;
    const int wbase16 = mtile * 16;
    unsigned haBase = (unsigned)__cvta_generic_to_shared(&S->ha[0][0]);
    unsigned a2Base = (unsigned)__cvta_generic_to_shared(&S->A2s[0][0]);
    const int m = l >> 3;
    const int arow   = wbase16 + (l & 7) + (m & 1) * 8;   // A ldmatrix row
    const int abyte  = (m >> 1) * 16;                      // A k-half select
    const int bcol   = (m & 1) * 8 + (l & 7);              // B ldmatrix col offset
    const int bbyte  = (m >> 1) * 16;                      // B k-half select
    float ab2r[4][2];
    #pragma unroll
    for (int nt = 0; nt < 4; ++nt) {
        ab2r[nt][0] = S->ab2s[cbase + nt * 8 + 2 * (l & 3)];
        ab2r[nt][1] = S->ab2s[cbase + nt * 8 + 2 * (l & 3) + 1];
    }

    const int wbase8 = w * 8;

    for (int it = 0; it < ITER; ++it) {
        const int blockBase = (blockIdx.x * ITER + it) * TILE_E;

        if (t < TILE_E) {
            int e = blockBase + t;
            int s = 0, g = 0, ms = -1; float pen = 0.f;
            if (e < E) {
                s = __ldcs(&edges[2 * e]); g = __ldcs(&edges[2 * e + 1]);
                int sa = army[s], ta = army[g];
                ms = sa - 1;
                if (sa <= 2 || ta >= 3 * sa) pen += 1.f;
                if (s == g) pen += 100.f;
            }
            S->srcs[t] = s; S->tgts[t] = g; S->maxsend[t] = ms; S->pen[t] = pen;
        }
        __syncthreads();

        // Phase 1: 4 iterations x 2 edges/warp (lane halves), double-buffered.
        uint4 wsv[2], wtv[2];
        uint2 pav[2], ptv[2];
        {
            const int le = wbase8 + half;
            const size_t sB = (size_t)S->srcs[le] * 768;
            const size_t tB = (size_t)S->tgts[le] * 768;
            wsv[0] = *(const uint4*)(projc + sB + f8 * 2);
            pav[0] = *(const uint2*)(projc + sB + 256 + f8);
            wtv[0] = *(const uint4*)(projc + tB + 384 + f8 * 2);
            ptv[0] = *(const uint2*)(projc + tB + 640 + f8);
        }

        #pragma unroll
        for (int i = 0; i < 4; ++i) {
            const int cur = i & 1, nxt = cur ^ 1;
            if (i < 3) {
                const int le = wbase8 + 2 * (i + 1) + half;
                const size_t sB = (size_t)S->srcs[le] * 768;
                const size_t tB = (size_t)S->tgts[le] * 768;
                wsv[nxt] = *(const uint4*)(projc + sB + f8 * 2);
                pav[nxt] = *(const uint2*)(projc + sB + 256 + f8);
                wtv[nxt] = *(const uint4*)(projc + tB + 384 + f8 * 2);
                ptv[nxt] = *(const uint2*)(projc + tB + 640 + f8);
            }
            const int le = wbase8 + 2 * i + half;
            const int e  = blockBase + le;

            __half2 sw[4], tw[4];
            sw[0] = *(__half2*)&wsv[cur].x; sw[1] = *(__half2*)&wsv[cur].y;
            sw[2] = *(__half2*)&wsv[cur].z; sw[3] = *(__half2*)&wsv[cur].w;
            tw[0] = *(__half2*)&wtv[cur].x; tw[1] = *(__half2*)&wtv[cur].y;
            tw[2] = *(__half2*)&wtv[cur].z; tw[3] = *(__half2*)&wtv[cur].w;
            __half2 acc2 = zero2;
            #pragma unroll
            for (int q = 0; q < 4; ++q) {
                __half2 h = __hmax2(__hadd2(__hadd2(sw[q], tw[q]), b1h[q]), zero2);
                acc2 = __hfma2(h, w2h[q], acc2);
            }
            float2 pf = __half22float2(acc2);
            float part = pf.x + pf.y;
            #pragma unroll
            for (int d = 8; d > 0; d >>= 1)
                part += __shfl_xor_sync(0xffffffffu, part, d);
            if (fl == 0 && e < E) __stcs(&out[e], part + b2v - S->pen[le]);

            // army hidden -> e4m3 smem
            uint sa01, sa23, sa45, sa67, ta01, ta23, ta45, ta67;
            unpack_e4m3_4(pav[cur].x, sa01, sa23);
            unpack_e4m3_4(pav[cur].y, sa45, sa67);
            unpack_e4m3_4(ptv[cur].x, ta01, ta23);
            unpack_e4m3_4(ptv[cur].y, ta45, ta67);
            __half2 g0 = __hmax2(__hadd2(__hadd2(*(__half2*)&sa01, *(__half2*)&ta01), ab1h[0]), zero2);
            __half2 g1 = __hmax2(__hadd2(__hadd2(*(__half2*)&sa23, *(__half2*)&ta23), ab1h[1]), zero2);
            __half2 g2 = __hmax2(__hadd2(__hadd2(*(__half2*)&sa45, *(__half2*)&ta45), ab1h[2]), zero2);
            __half2 g3 = __hmax2(__hadd2(__hadd2(*(__half2*)&sa67, *(__half2*)&ta67), ab1h[3]), zero2);
            unsigned short q0 = cvt_f16x2_e4m3x2(*(uint*)&g0);
            unsigned short q1 = cvt_f16x2_e4m3x2(*(uint*)&g1);
            unsigned short q2 = cvt_f16x2_e4m3x2(*(uint*)&g2);
            unsigned short q3 = cvt_f16x2_e4m3x2(*(uint*)&g3);
            uint2 stv;
            asm("mov.b32 %0, {%1, %2};" : "=r"(stv.x) : "h"(q0), "h"(q1));
            asm("mov.b32 %0, {%1, %2};" : "=r"(stv.y) : "h"(q2), "h"(q3));
            *(uint2*)&S->ha[le][f8] = stv;
        }
        __syncthreads();

        // Phase 2: army GEMM, fp8 m16n8k32.
        float c[4][4];
        #pragma unroll
        for (int nt = 0; nt < 4; ++nt) {
            c[nt][0] = ab2r[nt][0]; c[nt][1] = ab2r[nt][1];
            c[nt][2] = ab2r[nt][0]; c[nt][3] = ab2r[nt][1];
        }

        #pragma unroll
        for (int ks = 0; ks < 4; ++ks) {
            const int kb = ks * 32;
            unsigned a0, a1, a2, a3;
            unsigned aaddr = haBase + (unsigned)(arow * 144 + kb + abyte);
            asm volatile("ldmatrix.sync.aligned.m8n8.x4.shared.b16 {%0,%1,%2,%3}, [%4];"
                         : "=r"(a0), "=r"(a1), "=r"(a2), "=r"(a3) : "r"(aaddr));
            #pragma unroll
            for (int g2i = 0; g2i < 2; ++g2i) {
                unsigned b0, b1r, b2r, b3r;
                unsigned baddr = a2Base + (unsigned)((cbase + g2i * 16 + bcol) * 144 + kb + bbyte);
                asm volatile("ldmatrix.sync.aligned.m8n8.x4.shared.b16 {%0,%1,%2,%3}, [%4];"
                             : "=r"(b0), "=r"(b1r), "=r"(b2r), "=r"(b3r) : "r"(baddr));
                asm volatile("mma.sync.aligned.m16n8k32.row.col.f32.e4m3.e4m3.f32 "
                             "{%0,%1,%2,%3},{%4,%5,%6,%7},{%8,%9},{%0,%1,%2,%3};"
                             : "+f"(c[2*g2i][0]), "+f"(c[2*g2i][1]), "+f"(c[2*g2i][2]), "+f"(c[2*g2i][3])
                             : "r"(a0), "r"(a1), "r"(a2), "r"(a3), "r"(b0), "r"(b2r));
                asm volatile("mma.sync.aligned.m16n8k32.row.col.f32.e4m3.e4m3.f32 "
                             "{%0,%1,%2,%3},{%4,%5,%6,%7},{%8,%9},{%0,%1,%2,%3};"
                             : "+f"(c[2*g2i+1][0]), "+f"(c[2*g2i+1][1]), "+f"(c[2*g2i+1][2]), "+f"(c[2*g2i+1][3])
                             : "r"(a0), "r"(a1), "r"(a2), "r"(a3), "r"(b1r), "r"(b3r));
            }
        }

        // Epilogue.
        const int r0 = wbase16 + (l >> 2);
        const int e0 = blockBase + r0;
        const int e1 = e0 + 8;
        const int ms0 = S->maxsend[r0];
        const int ms1 = S->maxsend[r0 + 8];
        #pragma unroll
        for (int nt = 0; nt < 4; ++nt) {
            const int col = cbase + nt * 8 + 2 * (l & 3);
            if (e0 < E) {
                float2 v;
                v.x = (col     <= ms0) ? c[nt][0] : -1.0e9f;
                v.y = (col + 1 <= ms0) ? c[nt][1] : -1.0e9f;
                __stcs((float2*)&out[(size_t)E + (size_t)e0 * 64 + col], v);
            }
            if (e1 < E) {
                float2 v;
                v.x = (col     <= ms1) ? c[nt][2] : -1.0e9f;
                v.y = (col + 1 <= ms1) ? c[nt][3] : -1.0e9f;
                __stcs((float2*)&out[(size_t)E + (size_t)e1 * 64 + col], v);
            }
        }
        __syncthreads();
    }
}

// ---------------------------------------------------------------- launch ----
extern "C" void kernel_launch(void* const* d_in, const int* in_sizes, int n_in,
                              void* d_out, int out_size)
{
    const float* emb   = (const float*)d_in[0];
    const int*   edges = (const int*)  d_in[1];
    const int*   army  = (const int*)  d_in[2];
    const float* W1    = (const float*)d_in[3];
    const float* b1    = (const float*)d_in[4];
    const float* W2    = (const float*)d_in[5];
    const float* b2    = (const float*)d_in[6];
    const float* A1    = (const float*)d_in[7];
    const float* ab1   = (const float*)d_in[8];
    const float* A2    = (const float*)d_in[9];
    const float* ab2   = (const float*)d_in[10];
    float* out = (float*)d_out;

    int N = in_sizes[0] / 128;
    int E = in_sizes[1] / 2;
    if (N > MAX_N) N = MAX_N;

    a2prep_kernel<<<1, 256>>>(A2, ab2);
    wprep_kernel<<<2, 256>>>(W1, A1);

    cudaFuncSetAttribute(precompute_kernel,
                         cudaFuncAttributeMaxDynamicSharedMemorySize, S1_TOTAL);
    precompute_kernel<<<(N + 63) / 64, 256, S1_TOTAL>>>(emb, N);

    cudaFuncSetAttribute(edge_kernel, cudaFuncAttributeMaxDynamicSharedMemorySize,
                         (int)sizeof(S2));
    int eblk = (E + TILE_E * ITER - 1) / (TILE_E * ITER);
    edge_kernel<<<eblk, 256, sizeof(S2)>>>(
        edges, army, b1, W2, b2, ab1, out, E);
}